// round 5
// baseline (speedup 1.0000x reference)
#include <cuda_runtime.h>
#include <cuda_fp16.h>
#include <cuda_fp8.h>
#include <cstdint>
#include <math.h>

#define NV      6890
#define NPTS    16384
#define SPLIT   4
#define KRANGE  1723
#define LDF     704

// ---------------- scratch (device globals) -----------------------------------
__device__ __align__(16) __half  g_featH[(size_t)NPTS * LDF];
__device__ __align__(16) uint8_t g_feat8h[(size_t)NPTS * LDF];
__device__ __align__(16) uint8_t g_feat8l[(size_t)NPTS * LDF];
__device__ __align__(16) __half  g_h1H[(size_t)NPTS * 256];
__device__ __align__(16) uint8_t g_h18h[(size_t)NPTS * 256];
__device__ __align__(16) uint8_t g_h18l[(size_t)NPTS * 256];
__device__ __align__(16) __half  g_h2H[(size_t)NPTS * 256];
__device__ __align__(16) uint8_t g_h28h[(size_t)NPTS * 256];
__device__ __align__(16) uint8_t g_h28l[(size_t)NPTS * 256];
__device__ __align__(16) __half  g_W1H[(size_t)256 * LDF];
__device__ __align__(16) uint8_t g_W18h[(size_t)256 * LDF];
__device__ __align__(16) uint8_t g_W18l[(size_t)256 * LDF];
__device__ __align__(16) __half  g_W2H[(size_t)256 * 256];
__device__ __align__(16) uint8_t g_W28h[(size_t)256 * 256];
__device__ __align__(16) uint8_t g_W28l[(size_t)256 * 256];
__device__ __align__(16) __half  g_W3H[(size_t)256 * 256];
__device__ __align__(16) uint8_t g_W38h[(size_t)256 * 256];
__device__ __align__(16) uint8_t g_W38l[(size_t)256 * 256];
__device__ float                 g_Rinv[NV * 9];
__device__ int                   g_knn[NPTS];
__device__ unsigned long long    g_part[SPLIT * NPTS];

#define LO_SCALE 1024.0f
#define INV_LO   (1.0f / 1024.0f)

// ======================= small PTX helpers ===================================
__device__ __forceinline__ uint32_t smem_u32(const void* p) {
    uint32_t a;
    asm("{ .reg .u64 t; cvta.to.shared.u64 t, %1; cvt.u32.u64 %0, t; }" : "=r"(a) : "l"(p));
    return a;
}
__device__ __forceinline__ void cpa16(uint32_t dst, const void* src) {
    asm volatile("cp.async.cg.shared.global [%0], [%1], 16;" :: "r"(dst), "l"(src));
}
#define CPA_COMMIT() asm volatile("cp.async.commit_group;" ::: "memory")

__device__ __forceinline__ void ldm4(uint32_t* r, uint32_t addr) {
    asm volatile("ldmatrix.sync.aligned.m8n8.x4.shared.b16 {%0,%1,%2,%3}, [%4];"
                 : "=r"(r[0]), "=r"(r[1]), "=r"(r[2]), "=r"(r[3]) : "r"(addr));
}
__device__ __forceinline__ void mma16816(float* c, const uint32_t* a, uint32_t b0, uint32_t b1) {
    asm volatile(
        "mma.sync.aligned.m16n8k16.row.col.f32.f16.f16.f32 "
        "{%0,%1,%2,%3}, {%4,%5,%6,%7}, {%8,%9}, {%0,%1,%2,%3};"
        : "+f"(c[0]), "+f"(c[1]), "+f"(c[2]), "+f"(c[3])
        : "r"(a[0]), "r"(a[1]), "r"(a[2]), "r"(a[3]), "r"(b0), "r"(b1));
}
__device__ __forceinline__ void qmma(float* c, const uint32_t* a, uint32_t b0, uint32_t b1) {
    asm volatile(
        "mma.sync.aligned.m16n8k32.row.col.f32.e4m3.e4m3.f32 "
        "{%0,%1,%2,%3}, {%4,%5,%6,%7}, {%8,%9}, {%0,%1,%2,%3};"
        : "+f"(c[0]), "+f"(c[1]), "+f"(c[2]), "+f"(c[3])
        : "r"(a[0]), "r"(a[1]), "r"(a[2]), "r"(a[3]), "r"(b0), "r"(b1));
}

// write fp32 value as (fp16 hi, e4m3(hi-ish), e4m3(lo*1024))
__device__ __forceinline__ void wsplit3(__half* H, uint8_t* E8, uint8_t* L8, size_t i, float v) {
    __half h = __float2half_rn(v);
    float hf = __half2float(h);
    H[i]  = h;
    E8[i] = (uint8_t)__nv_cvt_float_to_fp8(v, __NV_SATFINITE, __NV_E4M3);
    L8[i] = (uint8_t)__nv_cvt_float_to_fp8((v - hf) * LO_SCALE, __NV_SATFINITE, __NV_E4M3);
}

// ---------------- accurate fp32 sincos (no FP64) -----------------------------
__device__ __forceinline__ void sincos_acc(float x, float* s, float* c) {
    const float C1 = 6.28125f;
    const float C2 = (float)1.9353071795864769e-3;
    const float C3 = (float)(6.283185307179586476925286766559 - 6.28125 -
                             (double)((float)1.9353071795864769e-3));
    float q = rintf(x * 0.15915494309189535f);
    float r = fmaf(q, -C1, x);
    r = fmaf(q, -C2, r);
    r = fmaf(q, -C3, r);
    sincosf(r, s, c);
}

// ---------------- kernel 1: invert 4x4 per vertex ----------------------------
__global__ void invert_kernel(const float* __restrict__ trans) {
    int v = blockIdx.x * blockDim.x + threadIdx.x;
    if (v >= NV) return;
    float m[16];
#pragma unroll
    for (int k = 0; k < 16; k++) m[k] = trans[k * NV + v];

    float i0  =  m[5]*m[10]*m[15] - m[5]*m[11]*m[14] - m[9]*m[6]*m[15] + m[9]*m[7]*m[14] + m[13]*m[6]*m[11] - m[13]*m[7]*m[10];
    float i4  = -m[4]*m[10]*m[15] + m[4]*m[11]*m[14] + m[8]*m[6]*m[15] - m[8]*m[7]*m[14] - m[12]*m[6]*m[11] + m[12]*m[7]*m[10];
    float i8  =  m[4]*m[9]*m[15]  - m[4]*m[11]*m[13] - m[8]*m[5]*m[15] + m[8]*m[7]*m[13] + m[12]*m[5]*m[11] - m[12]*m[7]*m[9];
    float i12 = -m[4]*m[9]*m[14]  + m[4]*m[10]*m[13] + m[8]*m[5]*m[14] - m[8]*m[6]*m[13] - m[12]*m[5]*m[10] + m[12]*m[6]*m[9];
    float i1  = -m[1]*m[10]*m[15] + m[1]*m[11]*m[14] + m[9]*m[2]*m[15] - m[9]*m[3]*m[14] - m[13]*m[2]*m[11] + m[13]*m[3]*m[10];
    float i5  =  m[0]*m[10]*m[15] - m[0]*m[11]*m[14] - m[8]*m[2]*m[15] + m[8]*m[3]*m[14] + m[12]*m[2]*m[11] - m[12]*m[3]*m[10];
    float i9  = -m[0]*m[9]*m[15]  + m[0]*m[11]*m[13] + m[8]*m[1]*m[15] - m[8]*m[3]*m[13] - m[12]*m[1]*m[11] + m[12]*m[3]*m[9];
    float i2  =  m[1]*m[6]*m[15]  - m[1]*m[7]*m[14]  - m[5]*m[2]*m[15] + m[5]*m[3]*m[14] + m[13]*m[2]*m[7]  - m[13]*m[3]*m[6];
    float i6  = -m[0]*m[6]*m[15]  + m[0]*m[7]*m[14]  + m[4]*m[2]*m[15] - m[4]*m[3]*m[14] - m[12]*m[2]*m[7]  + m[12]*m[3]*m[6];
    float i10 =  m[0]*m[5]*m[15]  - m[0]*m[7]*m[13]  - m[4]*m[1]*m[15] + m[4]*m[3]*m[13] + m[12]*m[1]*m[7]  - m[12]*m[3]*m[5];

    float det = m[0]*i0 + m[1]*i4 + m[2]*i8 + m[3]*i12;
    float id  = 1.0f / det;
    float* R = g_Rinv + v * 9;
    R[0] = i0*id;  R[1] = i1*id;  R[2] = i2*id;
    R[3] = i4*id;  R[4] = i5*id;  R[5] = i6*id;
    R[6] = i8*id;  R[7] = i9*id;  R[8] = i10*id;
}

// ---------------- kernel 2: KNN ----------------------------------------------
__global__ __launch_bounds__(256) void knn_kernel(const float* __restrict__ pts,
                                                  const float* __restrict__ kp) {
    __shared__ float4 sk[KRANGE];
    int pt = blockIdx.x * 256 + threadIdx.x;
    int ks = blockIdx.y * KRANGE;
    int ke = min(ks + KRANGE, NV);
    int n  = ke - ks;

    for (int i = threadIdx.x; i < n; i += 256) {
        int vv = ks + i;
        float kx = kp[vv*3], ky = kp[vv*3+1], kz = kp[vv*3+2];
        sk[i] = make_float4(kx, ky, kz, -0.5f*(kx*kx + ky*ky + kz*kz));
    }
    __syncthreads();

    float px = pts[pt*6], py = pts[pt*6+1], pz = pts[pt*6+2];
    float best = -1e30f; int bi = ks;

    int i = 0;
#pragma unroll 1
    for (; i + 4 <= n; i += 4) {
#pragma unroll
        for (int u = 0; u < 4; u++) {
            float4 k = sk[i+u];
            float s = fmaf(px, k.x, fmaf(py, k.y, fmaf(pz, k.z, k.w)));
            if (s > best) { best = s; bi = ks + i + u; }
        }
    }
    for (; i < n; i++) {
        float4 k = sk[i];
        float s = fmaf(px, k.x, fmaf(py, k.y, fmaf(pz, k.z, k.w)));
        if (s > best) { best = s; bi = ks + i; }
    }
    float mneg = -best;
    unsigned int ub = __float_as_uint(mneg);
    ub = (ub & 0x80000000u) ? ~ub : (ub | 0x80000000u);
    g_part[blockIdx.y * NPTS + pt] = ((unsigned long long)ub << 32) | (unsigned int)bi;
}

__global__ void knn_reduce() {
    int pt = blockIdx.x * blockDim.x + threadIdx.x;
    if (pt >= NPTS) return;
    unsigned long long b = g_part[pt];
#pragma unroll
    for (int s = 1; s < SPLIT; s++) {
        unsigned long long o = g_part[s * NPTS + pt];
        if (o < b) b = o;
    }
    g_knn[pt] = (int)(b & 0xFFFFFFFFull);
}

// ---------------- kernel 3: feature build (double-angle recurrence) ----------
__global__ __launch_bounds__(256) void feat_kernel(const float* __restrict__ pts,
                                                   const float* __restrict__ kp,
                                                   const int*   __restrict__ nbr,
                                                   const float* __restrict__ rest,
                                                   const float* __restrict__ lat,
                                                   float*       __restrict__ out) {
    int gw   = (blockIdx.x * blockDim.x + threadIdx.x) >> 5;
    int lane = threadIdx.x & 31;
    if (gw >= NPTS) return;

    float px = pts[gw*6], py = pts[gw*6+1], pz = pts[gw*6+2];
    int kidx = g_knn[gw];

    int vj = (lane < 7) ? nbr[kidx*7 + lane] : 0;
    int j  = (lane < 21) ? (lane / 3) : ((lane < 28) ? (lane - 21) : 0);
    int v  = __shfl_sync(0xffffffffu, vj, j);

    float vf = 0.0f;
    if (lane < 21) {
        vf = rest[v*3 + (lane % 3)];
    } else if (lane < 28) {
        float dx = px - kp[v*3], dy = py - kp[v*3+1], dz = pz - kp[v*3+2];
        vf = sqrtf(dx*dx + dy*dy + dz*dz);
    }

    size_t base = (size_t)gw * LDF;
    if (lane < 28) {
        wsplit3(g_featH, g_feat8h, g_feat8l, base + lane, vf);
        float s, c;
        sincos_acc(vf, &s, &c);
#pragma unroll
        for (int k = 0; k < 10; k++) {
            wsplit3(g_featH, g_feat8h, g_feat8l, base + 28  + k*28 + lane, s);
            wsplit3(g_featH, g_feat8h, g_feat8l, base + 308 + k*28 + lane, c);
            float sn = 2.0f * s * c;
            float cn = fmaf(-2.0f * s, s, 1.0f);
            s = sn; c = cn;
        }
    }
    if (lane < 4) {
        g_featH[base + 700 + lane]  = __float2half_rn(0.0f);
        g_feat8h[base + 700 + lane] = 0;
        g_feat8l[base + 700 + lane] = 0;
    }

#pragma unroll
    for (int it = 0; it < 4; it++) {
        int l  = it * 32 + lane;
        int jj = (l < 112) ? (l >> 4) : 0;
        int vv = __shfl_sync(0xffffffffu, vj, jj);
        if (l < 112) wsplit3(g_featH, g_feat8h, g_feat8l, base + 588 + l, lat[vv*16 + (l & 15)]);
    }

    if (lane == 0) {
        float dx = px - kp[kidx*3], dy = py - kp[kidx*3+1], dz = pz - kp[kidx*3+2];
        const float* R = g_Rinv + kidx * 9;
        float d0 = R[0]*dx + R[1]*dy + R[2]*dz;
        float d1 = R[3]*dx + R[4]*dy + R[5]*dz;
        float d2 = R[6]*dx + R[7]*dy + R[8]*dz;
        float nn = sqrtf(d0*d0 + d1*d1 + d2*d2);
        float iv = 1.0f / fmaxf(nn, 1e-12f);
        d0 *= iv; d1 *= iv; d2 *= iv;
        float* op = out + (size_t)gw * 283 + 256;
        op[0] = d0; op[1] = d1; op[2] = d2;
        float dir[3] = {d0, d1, d2};
#pragma unroll
        for (int c = 0; c < 3; c++) {
            float s, cc;
            sincos_acc(dir[c], &s, &cc);
#pragma unroll
            for (int k = 0; k < 4; k++) {
                op[3  + k*3 + c] = s;
                op[15 + k*3 + c] = cc;
                float sn = 2.0f * s * cc;
                float cn = fmaf(-2.0f * s, s, 1.0f);
                s = sn; cc = cn;
            }
        }
    }
}

// ---------- weight transpose + 3-way split -----------------------------------
__global__ void transpose_split3(const float* __restrict__ W, int K,
                                 __half* __restrict__ Wh, uint8_t* __restrict__ W8h,
                                 uint8_t* __restrict__ W8l, int ldk) {
    __shared__ float tile[32][33];
    int kb = blockIdx.x * 32;
    int nb = blockIdx.y * 32;
    int tx = threadIdx.x, ty = threadIdx.y;
#pragma unroll
    for (int i = 0; i < 4; i++) {
        int k = kb + ty + i * 8;
        tile[ty + i * 8][tx] = (k < K) ? W[(size_t)k * 256 + nb + tx] : 0.0f;
    }
    __syncthreads();
#pragma unroll
    for (int i = 0; i < 4; i++) {
        int n = nb + ty + i * 8;
        wsplit3(Wh, W8h, W8l, (size_t)n * ldk + kb + tx, tile[tx][ty + i * 8]);
    }
}

// ---------------- kernel 4: fp16-main + fp8-correction GEMM ------------------
// CTA 128x128, 512 threads (16 warps, 4x4), warp tile 32x32.
// Main term: HMMA.16816 fp16 hi x hi (fp32 acc).
// Corrections: QMMA.16832 e4m3 (A_hi8 * B_lo8 + A_lo8 * B_hi8), scale 2^-10.
#define PADH    40                     // halves per fp16 smem row (80 B)
#define PAD8    48                     // bytes per fp8 smem row
#define OFF_AH  0
#define OFF_BH  10240
#define OFF_A8H 20480
#define OFF_A8L 26624
#define OFF_B8H 32768
#define OFF_B8L 38912
#define BUFB    45056
#define GEMM_SMEM (2 * BUFB)           // 90112

template <int OUTMODE>  // 0: fp32 out, no relu; 1: relu + split trio out
__global__ __launch_bounds__(512, 1) void gemm_split(
    const __half* __restrict__ Ah, const uint8_t* __restrict__ A8h,
    const uint8_t* __restrict__ A8l, int lda,
    const __half* __restrict__ Bh, const uint8_t* __restrict__ B8h,
    const uint8_t* __restrict__ B8l, int ldb,
    const float* __restrict__ bias,
    float* __restrict__ Cf, int ldc,
    __half* __restrict__ CH, uint8_t* __restrict__ C8h, uint8_t* __restrict__ C8l,
    int kchunks)
{
    extern __shared__ char sm[];
    const int tid  = threadIdx.x;
    const int wid  = tid >> 5, lane = tid & 31;
    const int g    = lane >> 2, t = lane & 3;
    const int m0   = blockIdx.x * 128, n0 = blockIdx.y * 128;
    const int m0w  = (wid >> 2) * 32, n0w = (wid & 3) * 32;

    float accM[2][4][4];   // main
    float accC[2][4][4];   // correction (scaled by 2^10)
#pragma unroll
    for (int mi = 0; mi < 2; mi++)
#pragma unroll
        for (int ni = 0; ni < 4; ni++)
#pragma unroll
            for (int q = 0; q < 4; q++) { accM[mi][ni][q] = 0.0f; accC[mi][ni][q] = 0.0f; }

    const uint32_t smb = smem_u32(sm);

    auto issue = [&](int ch, int buf) {
        const int k0 = ch * 32;
        uint32_t sb = smb + buf * BUFB;
        {   // fp16 tiles: 512 segs each -> 1 per thread per tile
            int r = tid >> 2, s = tid & 3;
            cpa16(sb + OFF_AH + r * 80 + s * 16, Ah + (size_t)(m0 + r) * lda + k0 + s * 8);
            cpa16(sb + OFF_BH + r * 80 + s * 16, Bh + (size_t)(n0 + r) * ldb + k0 + s * 8);
        }
        {   // fp8 tiles: 256 segs each; threads <256 do hi, >=256 do lo
            int h = tid >> 8;
            int t2 = tid & 255;
            int r = t2 >> 1, s = t2 & 1;
            const uint8_t* a8 = h ? A8l : A8h;
            const uint8_t* b8 = h ? B8l : B8h;
            uint32_t offA = h ? OFF_A8L : OFF_A8H;
            uint32_t offB = h ? OFF_B8L : OFF_B8H;
            cpa16(sb + offA + r * PAD8 + s * 16, a8 + (size_t)(m0 + r) * lda + k0 + s * 16);
            cpa16(sb + offB + r * PAD8 + s * 16, b8 + (size_t)(n0 + r) * ldb + k0 + s * 16);
        }
        CPA_COMMIT();
    };

    issue(0, 0);

    // fp16 ldmatrix thread addressing (verified in R4)
    const int arow = lane & 15;
    const int asel = (lane >> 4) << 3;
    const int brow = (lane & 7) + ((lane & 16) ? 8 : 0);
    const int bsel = (lane & 8) ? 8 : 0;
    // fp8 ldmatrix thread addressing
    const int a8row = lane & 15;
    const int a8off = (lane >> 4) * 16;
    const int b8row = ((lane >> 4) << 3) + (lane & 7);
    const int b8off = ((lane >> 3) & 1) * 16;

    for (int ch = 0; ch < kchunks; ch++) {
        if (ch + 1 < kchunks) {
            issue(ch + 1, (ch + 1) & 1);
            asm volatile("cp.async.wait_group 1;" ::: "memory");
        } else {
            asm volatile("cp.async.wait_group 0;" ::: "memory");
        }
        __syncthreads();

        uint32_t sb  = smb + (ch & 1) * BUFB;
        uint32_t sAh = sb + OFF_AH,  sBh = sb + OFF_BH;
        uint32_t sA8h = sb + OFF_A8H, sA8l = sb + OFF_A8L;
        uint32_t sB8h = sb + OFF_B8H, sB8l = sb + OFF_B8L;

        // ---- main fp16 part: 2 k-halves of 16 ----
#pragma unroll
        for (int ks = 0; ks < 2; ks++) {
            const int kc = ks * 16;
            uint32_t ah[2][4];
#pragma unroll
            for (int mi = 0; mi < 2; mi++)
                ldm4(ah[mi], sAh + (uint32_t)((m0w + mi * 16 + arow) * PADH + kc + asel) * 2);
#pragma unroll
            for (int p = 0; p < 2; p++) {
                uint32_t bh[4];
                ldm4(bh, sBh + (uint32_t)((n0w + p * 16 + brow) * PADH + kc + bsel) * 2);
#pragma unroll
                for (int q = 0; q < 2; q++)
#pragma unroll
                    for (int mi = 0; mi < 2; mi++)
                        mma16816(accM[mi][p * 2 + q], ah[mi], bh[q * 2], bh[q * 2 + 1]);
            }
        }

        // ---- fp8 correction part: full K=32 per MMA ----
        {
            uint32_t a8H[2][4], a8L[2][4];
#pragma unroll
            for (int mi = 0; mi < 2; mi++) {
                uint32_t off = (uint32_t)((m0w + mi * 16 + a8row) * PAD8 + a8off);
                ldm4(a8H[mi], sA8h + off);
                ldm4(a8L[mi], sA8l + off);
            }
#pragma unroll
            for (int p = 0; p < 2; p++) {
                uint32_t b8L[4], b8H[4];
                uint32_t off = (uint32_t)((n0w + p * 16 + b8row) * PAD8 + b8off);
                ldm4(b8L, sB8l + off);
                ldm4(b8H, sB8h + off);
#pragma unroll
                for (int q = 0; q < 2; q++)
#pragma unroll
                    for (int mi = 0; mi < 2; mi++) {
                        float* c = accC[mi][p * 2 + q];
                        qmma(c, a8H[mi], b8L[q * 2], b8L[q * 2 + 1]);  // hi * lo
                        qmma(c, a8L[mi], b8H[q * 2], b8H[q * 2 + 1]);  // lo * hi
                    }
            }
        }
        __syncthreads();
    }

    // epilogue
#pragma unroll
    for (int mi = 0; mi < 2; mi++) {
        int row = m0 + m0w + mi * 16 + g;
#pragma unroll
        for (int ni = 0; ni < 4; ni++) {
            int col = n0 + n0w + ni * 8 + 2 * t;
            float b0 = bias[col], b1 = bias[col + 1];
            float v0 = accM[mi][ni][0] + accC[mi][ni][0] * INV_LO + b0;
            float v1 = accM[mi][ni][1] + accC[mi][ni][1] * INV_LO + b1;
            float v2 = accM[mi][ni][2] + accC[mi][ni][2] * INV_LO + b0;
            float v3 = accM[mi][ni][3] + accC[mi][ni][3] * INV_LO + b1;
            if (OUTMODE == 1) {
                v0 = fmaxf(v0, 0.f); v1 = fmaxf(v1, 0.f);
                v2 = fmaxf(v2, 0.f); v3 = fmaxf(v3, 0.f);
                wsplit3(CH, C8h, C8l, (size_t)row * 256 + col,           v0);
                wsplit3(CH, C8h, C8l, (size_t)row * 256 + col + 1,       v1);
                wsplit3(CH, C8h, C8l, (size_t)(row + 8) * 256 + col,     v2);
                wsplit3(CH, C8h, C8l, (size_t)(row + 8) * 256 + col + 1, v3);
            } else {
                Cf[(size_t)row * ldc + col]           = v0;
                Cf[(size_t)row * ldc + col + 1]       = v1;
                Cf[(size_t)(row + 8) * ldc + col]     = v2;
                Cf[(size_t)(row + 8) * ldc + col + 1] = v3;
            }
        }
    }
}

// ---------------- launch -----------------------------------------------------
extern "C" void kernel_launch(void* const* d_in, const int* in_sizes, int n_in,
                              void* d_out, int out_size) {
    const float* pts   = (const float*)d_in[0];
    const float* kp    = (const float*)d_in[1];
    const float* trans = (const float*)d_in[2];
    const int*   nbr   = (const int*)  d_in[3];
    const float* rest  = (const float*)d_in[4];
    const float* lat   = (const float*)d_in[5];
    const float* W1    = (const float*)d_in[6];
    const float* b1    = (const float*)d_in[7];
    const float* W2    = (const float*)d_in[8];
    const float* b2    = (const float*)d_in[9];
    const float* W3    = (const float*)d_in[10];
    const float* b3    = (const float*)d_in[11];
    float*       out   = (float*)d_out;

    void *pFH, *pF8h, *pF8l, *p1H, *p18h, *p18l, *p2H, *p28h, *p28l;
    void *w1H, *w18h, *w18l, *w2H, *w28h, *w28l, *w3H, *w38h, *w38l;
    cudaGetSymbolAddress(&pFH,  g_featH);
    cudaGetSymbolAddress(&pF8h, g_feat8h);
    cudaGetSymbolAddress(&pF8l, g_feat8l);
    cudaGetSymbolAddress(&p1H,  g_h1H);
    cudaGetSymbolAddress(&p18h, g_h18h);
    cudaGetSymbolAddress(&p18l, g_h18l);
    cudaGetSymbolAddress(&p2H,  g_h2H);
    cudaGetSymbolAddress(&p28h, g_h28h);
    cudaGetSymbolAddress(&p28l, g_h28l);
    cudaGetSymbolAddress(&w1H,  g_W1H);
    cudaGetSymbolAddress(&w18h, g_W18h);
    cudaGetSymbolAddress(&w18l, g_W18l);
    cudaGetSymbolAddress(&w2H,  g_W2H);
    cudaGetSymbolAddress(&w28h, g_W28h);
    cudaGetSymbolAddress(&w28l, g_W28l);
    cudaGetSymbolAddress(&w3H,  g_W3H);
    cudaGetSymbolAddress(&w38h, g_W38h);
    cudaGetSymbolAddress(&w38l, g_W38l);

    cudaFuncSetAttribute((const void*)gemm_split<0>, cudaFuncAttributeMaxDynamicSharedMemorySize, GEMM_SMEM);
    cudaFuncSetAttribute((const void*)gemm_split<1>, cudaFuncAttributeMaxDynamicSharedMemorySize, GEMM_SMEM);

    invert_kernel<<<(NV + 127) / 128, 128>>>(trans);
    knn_kernel<<<dim3(NPTS / 256, SPLIT), 256>>>(pts, kp);
    knn_reduce<<<NPTS / 256, 256>>>();
    feat_kernel<<<NPTS / 8, 256>>>(pts, kp, nbr, rest, lat, out);

    transpose_split3<<<dim3(LDF / 32, 8), dim3(32, 8)>>>(W1, 700, (__half*)w1H, (uint8_t*)w18h, (uint8_t*)w18l, LDF);
    transpose_split3<<<dim3(256 / 32, 8), dim3(32, 8)>>>(W2, 256, (__half*)w2H, (uint8_t*)w28h, (uint8_t*)w28l, 256);
    transpose_split3<<<dim3(256 / 32, 8), dim3(32, 8)>>>(W3, 256, (__half*)w3H, (uint8_t*)w38h, (uint8_t*)w38l, 256);

    dim3 ggrid(NPTS / 128, 2);
    gemm_split<1><<<ggrid, 512, GEMM_SMEM>>>(
        (const __half*)pFH, (const uint8_t*)pF8h, (const uint8_t*)pF8l, LDF,
        (const __half*)w1H, (const uint8_t*)w18h, (const uint8_t*)w18l, LDF,
        b1, nullptr, 0, (__half*)p1H, (uint8_t*)p18h, (uint8_t*)p18l, LDF / 32);
    gemm_split<1><<<ggrid, 512, GEMM_SMEM>>>(
        (const __half*)p1H, (const uint8_t*)p18h, (const uint8_t*)p18l, 256,
        (const __half*)w2H, (const uint8_t*)w28h, (const uint8_t*)w28l, 256,
        b2, nullptr, 0, (__half*)p2H, (uint8_t*)p28h, (uint8_t*)p28l, 256 / 32);
    gemm_split<0><<<ggrid, 512, GEMM_SMEM>>>(
        (const __half*)p2H, (const uint8_t*)p28h, (const uint8_t*)p28l, 256,
        (const __half*)w3H, (const uint8_t*)w38h, (const uint8_t*)w38l, 256,
        b3, out, 283, nullptr, nullptr, nullptr, 256 / 32);
}

// round 6
// speedup vs baseline: 1.4947x; 1.4947x over previous
#include <cuda_runtime.h>
#include <cuda_fp16.h>
#include <cstdint>
#include <math.h>

#define NV      6890
#define NPTS    16384
#define SPLIT   4
#define KRANGE  1723
#define LDF     704

// ---------------- scratch (device globals) -----------------------------------
__device__ __align__(16) __half  g_featH[(size_t)NPTS * LDF];
__device__ __align__(16) __half  g_featL[(size_t)NPTS * LDF];
__device__ __align__(16) __half  g_h1H[(size_t)NPTS * 256];
__device__ __align__(16) __half  g_h1L[(size_t)NPTS * 256];
__device__ __align__(16) __half  g_h2H[(size_t)NPTS * 256];
__device__ __align__(16) __half  g_h2L[(size_t)NPTS * 256];
__device__ __align__(16) __half  g_W1h[(size_t)256 * LDF];
__device__ __align__(16) __half  g_W1l[(size_t)256 * LDF];
__device__ __align__(16) __half  g_W2h[(size_t)256 * 256];
__device__ __align__(16) __half  g_W2l[(size_t)256 * 256];
__device__ __align__(16) __half  g_W3h[(size_t)256 * 256];
__device__ __align__(16) __half  g_W3l[(size_t)256 * 256];
__device__ float                 g_Rinv[NV * 9];
__device__ unsigned long long    g_part[SPLIT * NPTS];

// ======================= small PTX helpers ===================================
__device__ __forceinline__ uint32_t smem_u32(const void* p) {
    uint32_t a;
    asm("{ .reg .u64 t; cvta.to.shared.u64 t, %1; cvt.u32.u64 %0, t; }" : "=r"(a) : "l"(p));
    return a;
}
__device__ __forceinline__ void cpa16(uint32_t dst, const void* src) {
    asm volatile("cp.async.cg.shared.global [%0], [%1], 16;" :: "r"(dst), "l"(src));
}
#define CPA_COMMIT() asm volatile("cp.async.commit_group;" ::: "memory")

__device__ __forceinline__ void ldm4(uint32_t* r, uint32_t addr) {
    asm volatile("ldmatrix.sync.aligned.m8n8.x4.shared.b16 {%0,%1,%2,%3}, [%4];"
                 : "=r"(r[0]), "=r"(r[1]), "=r"(r[2]), "=r"(r[3]) : "r"(addr));
}
__device__ __forceinline__ void mma16816(float* c, const uint32_t* a, uint32_t b0, uint32_t b1) {
    asm volatile(
        "mma.sync.aligned.m16n8k16.row.col.f32.f16.f16.f32 "
        "{%0,%1,%2,%3}, {%4,%5,%6,%7}, {%8,%9}, {%0,%1,%2,%3};"
        : "+f"(c[0]), "+f"(c[1]), "+f"(c[2]), "+f"(c[3])
        : "r"(a[0]), "r"(a[1]), "r"(a[2]), "r"(a[3]), "r"(b0), "r"(b1));
}

__device__ __forceinline__ void wsplit(__half* H, __half* L, size_t idx, float v) {
    __half h = __float2half_rn(v);
    H[idx] = h;
    L[idx] = __float2half_rn(v - __half2float(h));
}

// ---------------- accurate fp32 sincos (no FP64) -----------------------------
__device__ __forceinline__ void sincos_acc(float x, float* s, float* c) {
    const float C1 = 6.28125f;
    const float C2 = (float)1.9353071795864769e-3;
    const float C3 = (float)(6.283185307179586476925286766559 - 6.28125 -
                             (double)((float)1.9353071795864769e-3));
    float q = rintf(x * 0.15915494309189535f);
    float r = fmaf(q, -C1, x);
    r = fmaf(q, -C2, r);
    r = fmaf(q, -C3, r);
    sincosf(r, s, c);
}

// ---------------- merged weight transpose + split (one launch) ---------------
__global__ void transpose_all(const float* __restrict__ W1, const float* __restrict__ W2,
                              const float* __restrict__ W3,
                              __half* __restrict__ W1h, __half* __restrict__ W1l,
                              __half* __restrict__ W2h, __half* __restrict__ W2l,
                              __half* __restrict__ W3h, __half* __restrict__ W3l) {
    int z = blockIdx.z;
    const float* W; __half *Wh, *Wl; int K, ldk;
    if (z == 0)      { W = W1; Wh = W1h; Wl = W1l; K = 700; ldk = LDF; }
    else if (z == 1) { W = W2; Wh = W2h; Wl = W2l; K = 256; ldk = 256; }
    else             { W = W3; Wh = W3h; Wl = W3l; K = 256; ldk = 256; }
    if (blockIdx.x * 32 >= ldk) return;

    __shared__ float tile[32][33];
    int kb = blockIdx.x * 32;
    int nb = blockIdx.y * 32;
    int tx = threadIdx.x, ty = threadIdx.y;   // 32 x 8
#pragma unroll
    for (int i = 0; i < 4; i++) {
        int k = kb + ty + i * 8;
        tile[ty + i * 8][tx] = (k < K) ? W[(size_t)k * 256 + nb + tx] : 0.0f;
    }
    __syncthreads();
#pragma unroll
    for (int i = 0; i < 4; i++) {
        int n = nb + ty + i * 8;
        wsplit(Wh, Wl, (size_t)n * ldk + kb + tx, tile[tx][ty + i * 8]);
    }
}

// ---------------- kernel 1: invert 4x4 per vertex ----------------------------
__global__ void invert_kernel(const float* __restrict__ trans) {
    int v = blockIdx.x * blockDim.x + threadIdx.x;
    if (v >= NV) return;
    float m[16];
#pragma unroll
    for (int k = 0; k < 16; k++) m[k] = trans[k * NV + v];

    float i0  =  m[5]*m[10]*m[15] - m[5]*m[11]*m[14] - m[9]*m[6]*m[15] + m[9]*m[7]*m[14] + m[13]*m[6]*m[11] - m[13]*m[7]*m[10];
    float i4  = -m[4]*m[10]*m[15] + m[4]*m[11]*m[14] + m[8]*m[6]*m[15] - m[8]*m[7]*m[14] - m[12]*m[6]*m[11] + m[12]*m[7]*m[10];
    float i8  =  m[4]*m[9]*m[15]  - m[4]*m[11]*m[13] - m[8]*m[5]*m[15] + m[8]*m[7]*m[13] + m[12]*m[5]*m[11] - m[12]*m[7]*m[9];
    float i12 = -m[4]*m[9]*m[14]  + m[4]*m[10]*m[13] + m[8]*m[5]*m[14] - m[8]*m[6]*m[13] - m[12]*m[5]*m[10] + m[12]*m[6]*m[9];
    float i1  = -m[1]*m[10]*m[15] + m[1]*m[11]*m[14] + m[9]*m[2]*m[15] - m[9]*m[3]*m[14] - m[13]*m[2]*m[11] + m[13]*m[3]*m[10];
    float i5  =  m[0]*m[10]*m[15] - m[0]*m[11]*m[14] - m[8]*m[2]*m[15] + m[8]*m[3]*m[14] + m[12]*m[2]*m[11] - m[12]*m[3]*m[10];
    float i9  = -m[0]*m[9]*m[15]  + m[0]*m[11]*m[13] + m[8]*m[1]*m[15] - m[8]*m[3]*m[13] - m[12]*m[1]*m[11] + m[12]*m[3]*m[9];
    float i2  =  m[1]*m[6]*m[15]  - m[1]*m[7]*m[14]  - m[5]*m[2]*m[15] + m[5]*m[3]*m[14] + m[13]*m[2]*m[7]  - m[13]*m[3]*m[6];
    float i6  = -m[0]*m[6]*m[15]  + m[0]*m[7]*m[14]  + m[4]*m[2]*m[15] - m[4]*m[3]*m[14] - m[12]*m[2]*m[7]  + m[12]*m[3]*m[6];
    float i10 =  m[0]*m[5]*m[15]  - m[0]*m[7]*m[13]  - m[4]*m[1]*m[15] + m[4]*m[3]*m[13] + m[12]*m[1]*m[7]  - m[12]*m[3]*m[5];

    float det = m[0]*i0 + m[1]*i4 + m[2]*i8 + m[3]*i12;
    float id  = 1.0f / det;
    float* R = g_Rinv + v * 9;
    R[0] = i0*id;  R[1] = i1*id;  R[2] = i2*id;
    R[3] = i4*id;  R[4] = i5*id;  R[5] = i6*id;
    R[6] = i8*id;  R[7] = i9*id;  R[8] = i10*id;
}

// ---------------- kernel 2: KNN ----------------------------------------------
__global__ __launch_bounds__(256) void knn_kernel(const float* __restrict__ pts,
                                                  const float* __restrict__ kp) {
    __shared__ float4 sk[KRANGE];
    int pt = blockIdx.x * 256 + threadIdx.x;
    int ks = blockIdx.y * KRANGE;
    int ke = min(ks + KRANGE, NV);
    int n  = ke - ks;

    for (int i = threadIdx.x; i < n; i += 256) {
        int vv = ks + i;
        float kx = kp[vv*3], ky = kp[vv*3+1], kz = kp[vv*3+2];
        sk[i] = make_float4(kx, ky, kz, -0.5f*(kx*kx + ky*ky + kz*kz));
    }
    __syncthreads();

    float px = pts[pt*6], py = pts[pt*6+1], pz = pts[pt*6+2];
    float best = -1e30f; int bi = ks;

    int i = 0;
#pragma unroll 1
    for (; i + 4 <= n; i += 4) {
#pragma unroll
        for (int u = 0; u < 4; u++) {
            float4 k = sk[i+u];
            float s = fmaf(px, k.x, fmaf(py, k.y, fmaf(pz, k.z, k.w)));
            if (s > best) { best = s; bi = ks + i + u; }
        }
    }
    for (; i < n; i++) {
        float4 k = sk[i];
        float s = fmaf(px, k.x, fmaf(py, k.y, fmaf(pz, k.z, k.w)));
        if (s > best) { best = s; bi = ks + i; }
    }
    float mneg = -best;
    unsigned int ub = __float_as_uint(mneg);
    ub = (ub & 0x80000000u) ? ~ub : (ub | 0x80000000u);
    g_part[blockIdx.y * NPTS + pt] = ((unsigned long long)ub << 32) | (unsigned int)bi;
}

// ---------------- kernel 3: feature build (fused knn-reduce + recurrence) ----
__global__ __launch_bounds__(256) void feat_kernel(const float* __restrict__ pts,
                                                   const float* __restrict__ kp,
                                                   const int*   __restrict__ nbr,
                                                   const float* __restrict__ rest,
                                                   const float* __restrict__ lat,
                                                   float*       __restrict__ out) {
    int gw   = (blockIdx.x * blockDim.x + threadIdx.x) >> 5;
    int lane = threadIdx.x & 31;
    if (gw >= NPTS) return;

    // fused 4-way knn reduce (min of packed u64)
    unsigned long long pv = (lane < SPLIT) ? g_part[(size_t)lane * NPTS + gw] : ~0ull;
    unsigned long long o;
    o = __shfl_xor_sync(0xffffffffu, pv, 1); if (o < pv) pv = o;
    o = __shfl_xor_sync(0xffffffffu, pv, 2); if (o < pv) pv = o;
    int kidx = (int)(__shfl_sync(0xffffffffu, pv, 0) & 0xFFFFFFFFull);

    float px = pts[gw*6], py = pts[gw*6+1], pz = pts[gw*6+2];

    int vj = (lane < 7) ? nbr[kidx*7 + lane] : 0;
    int j  = (lane < 21) ? (lane / 3) : ((lane < 28) ? (lane - 21) : 0);
    int v  = __shfl_sync(0xffffffffu, vj, j);

    float vf = 0.0f;
    if (lane < 21) {
        vf = rest[v*3 + (lane % 3)];
    } else if (lane < 28) {
        float dx = px - kp[v*3], dy = py - kp[v*3+1], dz = pz - kp[v*3+2];
        vf = sqrtf(dx*dx + dy*dy + dz*dz);
    }

    size_t base = (size_t)gw * LDF;
    if (lane < 28) {
        wsplit(g_featH, g_featL, base + lane, vf);
        float s, c;
        sincos_acc(vf, &s, &c);
#pragma unroll
        for (int k = 0; k < 10; k++) {
            wsplit(g_featH, g_featL, base + 28  + k*28 + lane, s);
            wsplit(g_featH, g_featL, base + 308 + k*28 + lane, c);
            float sn = 2.0f * s * c;
            float cn = fmaf(-2.0f * s, s, 1.0f);
            s = sn; c = cn;
        }
    }
    if (lane < 4) {
        g_featH[base + 700 + lane] = __float2half_rn(0.0f);
        g_featL[base + 700 + lane] = __float2half_rn(0.0f);
    }

#pragma unroll
    for (int it = 0; it < 4; it++) {
        int l  = it * 32 + lane;
        int jj = (l < 112) ? (l >> 4) : 0;
        int vv = __shfl_sync(0xffffffffu, vj, jj);
        if (l < 112) wsplit(g_featH, g_featL, base + 588 + l, lat[vv*16 + (l & 15)]);
    }

    if (lane == 0) {
        float dx = px - kp[kidx*3], dy = py - kp[kidx*3+1], dz = pz - kp[kidx*3+2];
        const float* R = g_Rinv + kidx * 9;
        float d0 = R[0]*dx + R[1]*dy + R[2]*dz;
        float d1 = R[3]*dx + R[4]*dy + R[5]*dz;
        float d2 = R[6]*dx + R[7]*dy + R[8]*dz;
        float nn = sqrtf(d0*d0 + d1*d1 + d2*d2);
        float iv = 1.0f / fmaxf(nn, 1e-12f);
        d0 *= iv; d1 *= iv; d2 *= iv;
        float* op = out + (size_t)gw * 283 + 256;
        op[0] = d0; op[1] = d1; op[2] = d2;
        float dir[3] = {d0, d1, d2};
#pragma unroll
        for (int c = 0; c < 3; c++) {
            float s, cc;
            sincos_acc(dir[c], &s, &cc);
#pragma unroll
            for (int k = 0; k < 4; k++) {
                op[3  + k*3 + c] = s;
                op[15 + k*3 + c] = cc;
                float sn = 2.0f * s * cc;
                float cn = fmaf(-2.0f * s, s, 1.0f);
                s = sn; cc = cn;
            }
        }
    }
}

// ---------------- kernel 4: fp16 3x-split HMMA GEMM (R4-proven) --------------
#define PADH   40
#define TILEB  (128 * PADH * 2)            // 10240 B per tile
#define BUFB   (4 * TILEB)                 // Ah, Al, Bh, Bl
#define GEMM_SMEM (2 * BUFB)               // 81920 B

template <int OUTMODE>  // 0: fp32 out, no relu; 1: relu + split fp16 hi/lo out
__global__ __launch_bounds__(256, 2) void gemm_hmma(
    const __half* __restrict__ Ah, const __half* __restrict__ Al, int lda,
    const __half* __restrict__ Bh, const __half* __restrict__ Bl, int ldb,
    const float* __restrict__ bias,
    float* __restrict__ Cf, int ldc,
    __half* __restrict__ ChH, __half* __restrict__ ChL,
    int kchunks)
{
    extern __shared__ char sm[];
    const int tid  = threadIdx.x;
    const int wid  = tid >> 5, lane = tid & 31;
    const int g    = lane >> 2, t = lane & 3;
    const int m0   = blockIdx.x * 128, n0 = blockIdx.y * 128;
    const int m0w  = (wid >> 1) * 32, n0w = (wid & 1) * 64;

    float acc[2][8][4];
#pragma unroll
    for (int mi = 0; mi < 2; mi++)
#pragma unroll
        for (int ni = 0; ni < 8; ni++)
#pragma unroll
            for (int q = 0; q < 4; q++) acc[mi][ni][q] = 0.0f;

    auto issue = [&](int ch, int buf) {
        const int k0 = ch * 32;
        char* base = sm + buf * BUFB;
#pragma unroll
        for (int i = 0; i < 2; i++) {
            int s = tid + i * 256;
            int r = s >> 2, c = (s & 3) * 8;
            uint32_t off = (uint32_t)(r * PADH + c) * 2;
            cpa16(smem_u32(base)             + off, Ah + (size_t)(m0 + r) * lda + k0 + c);
            cpa16(smem_u32(base + TILEB)     + off, Al + (size_t)(m0 + r) * lda + k0 + c);
            cpa16(smem_u32(base + 2 * TILEB) + off, Bh + (size_t)(n0 + r) * ldb + k0 + c);
            cpa16(smem_u32(base + 3 * TILEB) + off, Bl + (size_t)(n0 + r) * ldb + k0 + c);
        }
        CPA_COMMIT();
    };

    issue(0, 0);

    for (int ch = 0; ch < kchunks; ch++) {
        if (ch + 1 < kchunks) {
            issue(ch + 1, (ch + 1) & 1);
            asm volatile("cp.async.wait_group 1;" ::: "memory");
        } else {
            asm volatile("cp.async.wait_group 0;" ::: "memory");
        }
        __syncthreads();

        char* base = sm + (ch & 1) * BUFB;
        uint32_t sAh = smem_u32(base);
        uint32_t sAl = sAh + TILEB;
        uint32_t sBh = sAh + 2 * TILEB;
        uint32_t sBl = sAh + 3 * TILEB;

        const int arow = lane & 15;
        const int asel = (lane >> 4) << 3;
        const int brow = (lane & 7) + ((lane & 16) ? 8 : 0);
        const int bsel = (lane & 8) ? 8 : 0;

#pragma unroll
        for (int ks = 0; ks < 2; ks++) {
            const int kc = ks * 16;
            uint32_t ah[2][4], al[2][4];
#pragma unroll
            for (int mi = 0; mi < 2; mi++) {
                uint32_t off = (uint32_t)((m0w + mi * 16 + arow) * PADH + kc + asel) * 2;
                ldm4(ah[mi], sAh + off);
                ldm4(al[mi], sAl + off);
            }
#pragma unroll
            for (int p = 0; p < 4; p++) {
                uint32_t bh[4], bl[4];
                uint32_t off = (uint32_t)((n0w + p * 16 + brow) * PADH + kc + bsel) * 2;
                ldm4(bh, sBh + off);
                ldm4(bl, sBl + off);
#pragma unroll
                for (int q = 0; q < 2; q++) {
#pragma unroll
                    for (int mi = 0; mi < 2; mi++) {
                        float* c = acc[mi][p * 2 + q];
                        mma16816(c, ah[mi], bh[q * 2], bh[q * 2 + 1]);
                        mma16816(c, ah[mi], bl[q * 2], bl[q * 2 + 1]);
                        mma16816(c, al[mi], bh[q * 2], bh[q * 2 + 1]);
                    }
                }
            }
        }
        __syncthreads();
    }

#pragma unroll
    for (int mi = 0; mi < 2; mi++) {
        int row = m0 + m0w + mi * 16 + g;
#pragma unroll
        for (int ni = 0; ni < 8; ni++) {
            int col = n0 + n0w + ni * 8 + 2 * t;
            float b0 = bias[col], b1 = bias[col + 1];
            float v0 = acc[mi][ni][0] + b0;
            float v1 = acc[mi][ni][1] + b1;
            float v2 = acc[mi][ni][2] + b0;
            float v3 = acc[mi][ni][3] + b1;
            if (OUTMODE == 1) {
                v0 = fmaxf(v0, 0.f); v1 = fmaxf(v1, 0.f);
                v2 = fmaxf(v2, 0.f); v3 = fmaxf(v3, 0.f);
                __half h0 = __float2half_rn(v0), h1 = __float2half_rn(v1);
                __half h2 = __float2half_rn(v2), h3 = __float2half_rn(v3);
                __half l0 = __float2half_rn(v0 - __half2float(h0));
                __half l1 = __float2half_rn(v1 - __half2float(h1));
                __half l2 = __float2half_rn(v2 - __half2float(h2));
                __half l3 = __float2half_rn(v3 - __half2float(h3));
                *(__half2*)&ChH[(size_t)row * 256 + col]       = __halves2half2(h0, h1);
                *(__half2*)&ChL[(size_t)row * 256 + col]       = __halves2half2(l0, l1);
                *(__half2*)&ChH[(size_t)(row + 8) * 256 + col] = __halves2half2(h2, h3);
                *(__half2*)&ChL[(size_t)(row + 8) * 256 + col] = __halves2half2(l2, l3);
            } else {
                Cf[(size_t)row * ldc + col]           = v0;
                Cf[(size_t)row * ldc + col + 1]       = v1;
                Cf[(size_t)(row + 8) * ldc + col]     = v2;
                Cf[(size_t)(row + 8) * ldc + col + 1] = v3;
            }
        }
    }
}

// ---------------- launch -----------------------------------------------------
extern "C" void kernel_launch(void* const* d_in, const int* in_sizes, int n_in,
                              void* d_out, int out_size) {
    const float* pts   = (const float*)d_in[0];
    const float* kp    = (const float*)d_in[1];
    const float* trans = (const float*)d_in[2];
    const int*   nbr   = (const int*)  d_in[3];
    const float* rest  = (const float*)d_in[4];
    const float* lat   = (const float*)d_in[5];
    const float* W1    = (const float*)d_in[6];
    const float* b1    = (const float*)d_in[7];
    const float* W2    = (const float*)d_in[8];
    const float* b2    = (const float*)d_in[9];
    const float* W3    = (const float*)d_in[10];
    const float* b3    = (const float*)d_in[11];
    float*       out   = (float*)d_out;

    void *pFH, *pFL, *p1H, *p1L, *p2H, *p2L;
    void *w1h, *w1l, *w2h, *w2l, *w3h, *w3l;
    cudaGetSymbolAddress(&pFH, g_featH);
    cudaGetSymbolAddress(&pFL, g_featL);
    cudaGetSymbolAddress(&p1H, g_h1H);
    cudaGetSymbolAddress(&p1L, g_h1L);
    cudaGetSymbolAddress(&p2H, g_h2H);
    cudaGetSymbolAddress(&p2L, g_h2L);
    cudaGetSymbolAddress(&w1h, g_W1h);
    cudaGetSymbolAddress(&w1l, g_W1l);
    cudaGetSymbolAddress(&w2h, g_W2h);
    cudaGetSymbolAddress(&w2l, g_W2l);
    cudaGetSymbolAddress(&w3h, g_W3h);
    cudaGetSymbolAddress(&w3l, g_W3l);

    cudaFuncSetAttribute((const void*)gemm_hmma<0>, cudaFuncAttributeMaxDynamicSharedMemorySize, GEMM_SMEM);
    cudaFuncSetAttribute((const void*)gemm_hmma<1>, cudaFuncAttributeMaxDynamicSharedMemorySize, GEMM_SMEM);

    transpose_all<<<dim3(LDF / 32, 8, 3), dim3(32, 8)>>>(
        W1, W2, W3, (__half*)w1h, (__half*)w1l,
        (__half*)w2h, (__half*)w2l, (__half*)w3h, (__half*)w3l);
    invert_kernel<<<(NV + 127) / 128, 128>>>(trans);
    knn_kernel<<<dim3(NPTS / 256, SPLIT), 256>>>(pts, kp);
    feat_kernel<<<NPTS / 8, 256>>>(pts, kp, nbr, rest, lat, out);

    dim3 ggrid(NPTS / 128, 2);
    gemm_hmma<1><<<ggrid, 256, GEMM_SMEM>>>(
        (const __half*)pFH, (const __half*)pFL, LDF,
        (const __half*)w1h, (const __half*)w1l, LDF,
        b1, nullptr, 0, (__half*)p1H, (__half*)p1L, LDF / 32);
    gemm_hmma<1><<<ggrid, 256, GEMM_SMEM>>>(
        (const __half*)p1H, (const __half*)p1L, 256,
        (const __half*)w2h, (const __half*)w2l, 256,
        b2, nullptr, 0, (__half*)p2H, (__half*)p2L, 256 / 32);
    gemm_hmma<0><<<ggrid, 256, GEMM_SMEM>>>(
        (const __half*)p2H, (const __half*)p2L, 256,
        (const __half*)w3h, (const __half*)w3l, 256,
        b3, out, 283, nullptr, nullptr, 256 / 32);
}

// round 7
// speedup vs baseline: 1.5274x; 1.0219x over previous
#include <cuda_runtime.h>
#include <cuda_fp16.h>
#include <cstdint>
#include <math.h>

#define NV      6890
#define NPTS    16384
#define SPLIT   8
#define KRANGE  862      // ceil(6890/8)
#define LDF     704

// ---------------- scratch (device globals) -----------------------------------
__device__ __align__(16) __half  g_featH[(size_t)NPTS * LDF];
__device__ __align__(16) __half  g_featL[(size_t)NPTS * LDF];
__device__ __align__(16) __half  g_h1H[(size_t)NPTS * 256];
__device__ __align__(16) __half  g_h1L[(size_t)NPTS * 256];
__device__ __align__(16) __half  g_h2H[(size_t)NPTS * 256];
__device__ __align__(16) __half  g_h2L[(size_t)NPTS * 256];
__device__ __align__(16) __half  g_W1h[(size_t)256 * LDF];
__device__ __align__(16) __half  g_W1l[(size_t)256 * LDF];
__device__ __align__(16) __half  g_W2h[(size_t)256 * 256];
__device__ __align__(16) __half  g_W2l[(size_t)256 * 256];
__device__ __align__(16) __half  g_W3h[(size_t)256 * 256];
__device__ __align__(16) __half  g_W3l[(size_t)256 * 256];
__device__ float                 g_Rinv[NV * 9];
__device__ unsigned long long    g_part[SPLIT * NPTS];

// ======================= small PTX helpers ===================================
__device__ __forceinline__ uint32_t smem_u32(const void* p) {
    uint32_t a;
    asm("{ .reg .u64 t; cvta.to.shared.u64 t, %1; cvt.u32.u64 %0, t; }" : "=r"(a) : "l"(p));
    return a;
}
__device__ __forceinline__ void cpa16(uint32_t dst, const void* src) {
    asm volatile("cp.async.cg.shared.global [%0], [%1], 16;" :: "r"(dst), "l"(src));
}
#define CPA_COMMIT() asm volatile("cp.async.commit_group;" ::: "memory")

__device__ __forceinline__ void ldm4(uint32_t* r, uint32_t addr) {
    asm volatile("ldmatrix.sync.aligned.m8n8.x4.shared.b16 {%0,%1,%2,%3}, [%4];"
                 : "=r"(r[0]), "=r"(r[1]), "=r"(r[2]), "=r"(r[3]) : "r"(addr));
}
__device__ __forceinline__ void mma16816(float* c, const uint32_t* a, uint32_t b0, uint32_t b1) {
    asm volatile(
        "mma.sync.aligned.m16n8k16.row.col.f32.f16.f16.f32 "
        "{%0,%1,%2,%3}, {%4,%5,%6,%7}, {%8,%9}, {%0,%1,%2,%3};"
        : "+f"(c[0]), "+f"(c[1]), "+f"(c[2]), "+f"(c[3])
        : "r"(a[0]), "r"(a[1]), "r"(a[2]), "r"(a[3]), "r"(b0), "r"(b1));
}

__device__ __forceinline__ void wsplit(__half* H, __half* L, size_t idx, float v) {
    __half h = __float2half_rn(v);
    H[idx] = h;
    L[idx] = __float2half_rn(v - __half2float(h));
}

// ---------------- accurate fp32 sincos (no FP64) -----------------------------
__device__ __forceinline__ void sincos_acc(float x, float* s, float* c) {
    const float C1 = 6.28125f;
    const float C2 = (float)1.9353071795864769e-3;
    const float C3 = (float)(6.283185307179586476925286766559 - 6.28125 -
                             (double)((float)1.9353071795864769e-3));
    float q = rintf(x * 0.15915494309189535f);
    float r = fmaf(q, -C1, x);
    r = fmaf(q, -C2, r);
    r = fmaf(q, -C3, r);
    sincosf(r, s, c);
}

// ---------------- merged weight transpose + split (one launch) ---------------
__global__ void transpose_all(const float* __restrict__ W1, const float* __restrict__ W2,
                              const float* __restrict__ W3,
                              __half* __restrict__ W1h, __half* __restrict__ W1l,
                              __half* __restrict__ W2h, __half* __restrict__ W2l,
                              __half* __restrict__ W3h, __half* __restrict__ W3l) {
    int z = blockIdx.z;
    const float* W; __half *Wh, *Wl; int K, ldk;
    if (z == 0)      { W = W1; Wh = W1h; Wl = W1l; K = 700; ldk = LDF; }
    else if (z == 1) { W = W2; Wh = W2h; Wl = W2l; K = 256; ldk = 256; }
    else             { W = W3; Wh = W3h; Wl = W3l; K = 256; ldk = 256; }
    if (blockIdx.x * 32 >= ldk) return;

    __shared__ float tile[32][33];
    int kb = blockIdx.x * 32;
    int nb = blockIdx.y * 32;
    int tx = threadIdx.x, ty = threadIdx.y;
#pragma unroll
    for (int i = 0; i < 4; i++) {
        int k = kb + ty + i * 8;
        tile[ty + i * 8][tx] = (k < K) ? W[(size_t)k * 256 + nb + tx] : 0.0f;
    }
    __syncthreads();
#pragma unroll
    for (int i = 0; i < 4; i++) {
        int n = nb + ty + i * 8;
        wsplit(Wh, Wl, (size_t)n * ldk + kb + tx, tile[tx][ty + i * 8]);
    }
}

// ---------------- kernel 1: invert 4x4 per vertex ----------------------------
__global__ void invert_kernel(const float* __restrict__ trans) {
    int v = blockIdx.x * blockDim.x + threadIdx.x;
    if (v >= NV) return;
    float m[16];
#pragma unroll
    for (int k = 0; k < 16; k++) m[k] = trans[k * NV + v];

    float i0  =  m[5]*m[10]*m[15] - m[5]*m[11]*m[14] - m[9]*m[6]*m[15] + m[9]*m[7]*m[14] + m[13]*m[6]*m[11] - m[13]*m[7]*m[10];
    float i4  = -m[4]*m[10]*m[15] + m[4]*m[11]*m[14] + m[8]*m[6]*m[15] - m[8]*m[7]*m[14] - m[12]*m[6]*m[11] + m[12]*m[7]*m[10];
    float i8  =  m[4]*m[9]*m[15]  - m[4]*m[11]*m[13] - m[8]*m[5]*m[15] + m[8]*m[7]*m[13] + m[12]*m[5]*m[11] - m[12]*m[7]*m[9];
    float i12 = -m[4]*m[9]*m[14]  + m[4]*m[10]*m[13] + m[8]*m[5]*m[14] - m[8]*m[6]*m[13] - m[12]*m[5]*m[10] + m[12]*m[6]*m[9];
    float i1  = -m[1]*m[10]*m[15] + m[1]*m[11]*m[14] + m[9]*m[2]*m[15] - m[9]*m[3]*m[14] - m[13]*m[2]*m[11] + m[13]*m[3]*m[10];
    float i5  =  m[0]*m[10]*m[15] - m[0]*m[11]*m[14] - m[8]*m[2]*m[15] + m[8]*m[3]*m[14] + m[12]*m[2]*m[11] - m[12]*m[3]*m[10];
    float i9  = -m[0]*m[9]*m[15]  + m[0]*m[11]*m[13] + m[8]*m[1]*m[15] - m[8]*m[3]*m[13] - m[12]*m[1]*m[11] + m[12]*m[3]*m[9];
    float i2  =  m[1]*m[6]*m[15]  - m[1]*m[7]*m[14]  - m[5]*m[2]*m[15] + m[5]*m[3]*m[14] + m[13]*m[2]*m[7]  - m[13]*m[3]*m[6];
    float i6  = -m[0]*m[6]*m[15]  + m[0]*m[7]*m[14]  + m[4]*m[2]*m[15] - m[4]*m[3]*m[14] - m[12]*m[2]*m[7]  + m[12]*m[3]*m[6];
    float i10 =  m[0]*m[5]*m[15]  - m[0]*m[7]*m[13]  - m[4]*m[1]*m[15] + m[4]*m[3]*m[13] + m[12]*m[1]*m[7]  - m[12]*m[3]*m[5];

    float det = m[0]*i0 + m[1]*i4 + m[2]*i8 + m[3]*i12;
    float id  = 1.0f / det;
    float* R = g_Rinv + v * 9;
    R[0] = i0*id;  R[1] = i1*id;  R[2] = i2*id;
    R[3] = i4*id;  R[4] = i5*id;  R[5] = i6*id;
    R[6] = i8*id;  R[7] = i9*id;  R[8] = i10*id;
}

// ---------------- kernel 2: KNN, 8-way keypoint split -------------------------
__global__ __launch_bounds__(256) void knn_kernel(const float* __restrict__ pts,
                                                  const float* __restrict__ kp) {
    __shared__ float4 sk[KRANGE];
    int pt = blockIdx.x * 256 + threadIdx.x;
    int ks = blockIdx.y * KRANGE;
    int ke = min(ks + KRANGE, NV);
    int n  = ke - ks;

    for (int i = threadIdx.x; i < n; i += 256) {
        int vv = ks + i;
        float kx = kp[vv*3], ky = kp[vv*3+1], kz = kp[vv*3+2];
        sk[i] = make_float4(kx, ky, kz, -0.5f*(kx*kx + ky*ky + kz*kz));
    }
    __syncthreads();

    float px = pts[pt*6], py = pts[pt*6+1], pz = pts[pt*6+2];
    float best = -1e30f; int bi = ks;

    int i = 0;
#pragma unroll 1
    for (; i + 4 <= n; i += 4) {
#pragma unroll
        for (int u = 0; u < 4; u++) {
            float4 k = sk[i+u];
            float s = fmaf(px, k.x, fmaf(py, k.y, fmaf(pz, k.z, k.w)));
            if (s > best) { best = s; bi = ks + i + u; }
        }
    }
    for (; i < n; i++) {
        float4 k = sk[i];
        float s = fmaf(px, k.x, fmaf(py, k.y, fmaf(pz, k.z, k.w)));
        if (s > best) { best = s; bi = ks + i; }
    }
    float mneg = -best;
    unsigned int ub = __float_as_uint(mneg);
    ub = (ub & 0x80000000u) ? ~ub : (ub | 0x80000000u);
    g_part[blockIdx.y * NPTS + pt] = ((unsigned long long)ub << 32) | (unsigned int)bi;
}

// ---------------- kernel 3: feature build (fused knn-reduce + recurrence) ----
__global__ __launch_bounds__(256) void feat_kernel(const float* __restrict__ pts,
                                                   const float* __restrict__ kp,
                                                   const int*   __restrict__ nbr,
                                                   const float* __restrict__ rest,
                                                   const float* __restrict__ lat,
                                                   float*       __restrict__ out) {
    int gw   = (blockIdx.x * blockDim.x + threadIdx.x) >> 5;
    int lane = threadIdx.x & 31;
    if (gw >= NPTS) return;

    // fused 8-way knn reduce (min of packed u64)
    unsigned long long pv = (lane < SPLIT) ? g_part[(size_t)lane * NPTS + gw] : ~0ull;
    unsigned long long o;
    o = __shfl_xor_sync(0xffffffffu, pv, 1); if (o < pv) pv = o;
    o = __shfl_xor_sync(0xffffffffu, pv, 2); if (o < pv) pv = o;
    o = __shfl_xor_sync(0xffffffffu, pv, 4); if (o < pv) pv = o;
    int kidx = (int)(__shfl_sync(0xffffffffu, pv, 0) & 0xFFFFFFFFull);

    float px = pts[gw*6], py = pts[gw*6+1], pz = pts[gw*6+2];

    int vj = (lane < 7) ? nbr[kidx*7 + lane] : 0;
    int j  = (lane < 21) ? (lane / 3) : ((lane < 28) ? (lane - 21) : 0);
    int v  = __shfl_sync(0xffffffffu, vj, j);

    float vf = 0.0f;
    if (lane < 21) {
        vf = rest[v*3 + (lane % 3)];
    } else if (lane < 28) {
        float dx = px - kp[v*3], dy = py - kp[v*3+1], dz = pz - kp[v*3+2];
        vf = sqrtf(dx*dx + dy*dy + dz*dz);
    }

    size_t base = (size_t)gw * LDF;
    if (lane < 28) {
        wsplit(g_featH, g_featL, base + lane, vf);
        float s, c;
        sincos_acc(vf, &s, &c);
#pragma unroll
        for (int k = 0; k < 10; k++) {
            wsplit(g_featH, g_featL, base + 28  + k*28 + lane, s);
            wsplit(g_featH, g_featL, base + 308 + k*28 + lane, c);
            float sn = 2.0f * s * c;
            float cn = fmaf(-2.0f * s, s, 1.0f);
            s = sn; c = cn;
        }
    }
    if (lane < 4) {
        g_featH[base + 700 + lane] = __float2half_rn(0.0f);
        g_featL[base + 700 + lane] = __float2half_rn(0.0f);
    }

#pragma unroll
    for (int it = 0; it < 4; it++) {
        int l  = it * 32 + lane;
        int jj = (l < 112) ? (l >> 4) : 0;
        int vv = __shfl_sync(0xffffffffu, vj, jj);
        if (l < 112) wsplit(g_featH, g_featL, base + 588 + l, lat[vv*16 + (l & 15)]);
    }

    if (lane == 0) {
        float dx = px - kp[kidx*3], dy = py - kp[kidx*3+1], dz = pz - kp[kidx*3+2];
        const float* R = g_Rinv + kidx * 9;
        float d0 = R[0]*dx + R[1]*dy + R[2]*dz;
        float d1 = R[3]*dx + R[4]*dy + R[5]*dz;
        float d2 = R[6]*dx + R[7]*dy + R[8]*dz;
        float nn = sqrtf(d0*d0 + d1*d1 + d2*d2);
        float iv = 1.0f / fmaxf(nn, 1e-12f);
        d0 *= iv; d1 *= iv; d2 *= iv;
        float* op = out + (size_t)gw * 283 + 256;
        op[0] = d0; op[1] = d1; op[2] = d2;
        float dir[3] = {d0, d1, d2};
#pragma unroll
        for (int c = 0; c < 3; c++) {
            float s, cc;
            sincos_acc(dir[c], &s, &cc);
#pragma unroll
            for (int k = 0; k < 4; k++) {
                op[3  + k*3 + c] = s;
                op[15 + k*3 + c] = cc;
                float sn = 2.0f * s * cc;
                float cn = fmaf(-2.0f * s, s, 1.0f);
                s = sn; cc = cn;
            }
        }
    }
}

// ---------------- kernel 4: fp16 3x-split HMMA GEMM, ILP-reordered -----------
#define PADH   40
#define TILEB  (128 * PADH * 2)
#define BUFB   (4 * TILEB)
#define GEMM_SMEM (2 * BUFB)               // 81920 B

template <int OUTMODE>
__global__ __launch_bounds__(256, 2) void gemm_hmma(
    const __half* __restrict__ Ah, const __half* __restrict__ Al, int lda,
    const __half* __restrict__ Bh, const __half* __restrict__ Bl, int ldb,
    const float* __restrict__ bias,
    float* __restrict__ Cf, int ldc,
    __half* __restrict__ ChH, __half* __restrict__ ChL,
    int kchunks)
{
    extern __shared__ char sm[];
    const int tid  = threadIdx.x;
    const int wid  = tid >> 5, lane = tid & 31;
    const int g    = lane >> 2, t = lane & 3;
    const int m0   = blockIdx.x * 128, n0 = blockIdx.y * 128;
    const int m0w  = (wid >> 1) * 32, n0w = (wid & 1) * 64;

    float acc[2][8][4];
#pragma unroll
    for (int mi = 0; mi < 2; mi++)
#pragma unroll
        for (int ni = 0; ni < 8; ni++)
#pragma unroll
            for (int q = 0; q < 4; q++) acc[mi][ni][q] = 0.0f;

    auto issue = [&](int ch, int buf) {
        const int k0 = ch * 32;
        char* base = sm + buf * BUFB;
#pragma unroll
        for (int i = 0; i < 2; i++) {
            int s = tid + i * 256;
            int r = s >> 2, c = (s & 3) * 8;
            uint32_t off = (uint32_t)(r * PADH + c) * 2;
            cpa16(smem_u32(base)             + off, Ah + (size_t)(m0 + r) * lda + k0 + c);
            cpa16(smem_u32(base + TILEB)     + off, Al + (size_t)(m0 + r) * lda + k0 + c);
            cpa16(smem_u32(base + 2 * TILEB) + off, Bh + (size_t)(n0 + r) * ldb + k0 + c);
            cpa16(smem_u32(base + 3 * TILEB) + off, Bl + (size_t)(n0 + r) * ldb + k0 + c);
        }
        CPA_COMMIT();
    };

    issue(0, 0);

    for (int ch = 0; ch < kchunks; ch++) {
        if (ch + 1 < kchunks) {
            issue(ch + 1, (ch + 1) & 1);
            asm volatile("cp.async.wait_group 1;" ::: "memory");
        } else {
            asm volatile("cp.async.wait_group 0;" ::: "memory");
        }
        __syncthreads();

        char* base = sm + (ch & 1) * BUFB;
        uint32_t sAh = smem_u32(base);
        uint32_t sAl = sAh + TILEB;
        uint32_t sBh = sAh + 2 * TILEB;
        uint32_t sBl = sAh + 3 * TILEB;

        const int arow = lane & 15;
        const int asel = (lane >> 4) << 3;
        const int brow = (lane & 7) + ((lane & 16) ? 8 : 0);
        const int bsel = (lane & 8) ? 8 : 0;

#pragma unroll
        for (int ks = 0; ks < 2; ks++) {
            const int kc = ks * 16;
            uint32_t ah[2][4], al[2][4];
#pragma unroll
            for (int mi = 0; mi < 2; mi++) {
                uint32_t off = (uint32_t)((m0w + mi * 16 + arow) * PADH + kc + asel) * 2;
                ldm4(ah[mi], sAh + off);
                ldm4(al[mi], sAl + off);
            }
            // process B tiles in pairs; term-outer ordering inside each pair
            // gives 8 independent MMAs between reuses of any accumulator.
#pragma unroll
            for (int ph = 0; ph < 2; ph++) {
                uint32_t bh[2][4], bl[2][4];
#pragma unroll
                for (int pp = 0; pp < 2; pp++) {
                    int p = ph * 2 + pp;
                    uint32_t off = (uint32_t)((n0w + p * 16 + brow) * PADH + kc + bsel) * 2;
                    ldm4(bh[pp], sBh + off);
                    ldm4(bl[pp], sBl + off);
                }
                // term 0: hi*hi
#pragma unroll
                for (int pp = 0; pp < 2; pp++)
#pragma unroll
                    for (int q = 0; q < 2; q++)
#pragma unroll
                        for (int mi = 0; mi < 2; mi++)
                            mma16816(acc[mi][(ph*2+pp)*2+q], ah[mi], bh[pp][q*2], bh[pp][q*2+1]);
                // term 1: hi*lo
#pragma unroll
                for (int pp = 0; pp < 2; pp++)
#pragma unroll
                    for (int q = 0; q < 2; q++)
#pragma unroll
                        for (int mi = 0; mi < 2; mi++)
                            mma16816(acc[mi][(ph*2+pp)*2+q], ah[mi], bl[pp][q*2], bl[pp][q*2+1]);
                // term 2: lo*hi
#pragma unroll
                for (int pp = 0; pp < 2; pp++)
#pragma unroll
                    for (int q = 0; q < 2; q++)
#pragma unroll
                        for (int mi = 0; mi < 2; mi++)
                            mma16816(acc[mi][(ph*2+pp)*2+q], al[mi], bh[pp][q*2], bh[pp][q*2+1]);
            }
        }
        __syncthreads();
    }

#pragma unroll
    for (int mi = 0; mi < 2; mi++) {
        int row = m0 + m0w + mi * 16 + g;
#pragma unroll
        for (int ni = 0; ni < 8; ni++) {
            int col = n0 + n0w + ni * 8 + 2 * t;
            float b0 = bias[col], b1 = bias[col + 1];
            float v0 = acc[mi][ni][0] + b0;
            float v1 = acc[mi][ni][1] + b1;
            float v2 = acc[mi][ni][2] + b0;
            float v3 = acc[mi][ni][3] + b1;
            if (OUTMODE == 1) {
                v0 = fmaxf(v0, 0.f); v1 = fmaxf(v1, 0.f);
                v2 = fmaxf(v2, 0.f); v3 = fmaxf(v3, 0.f);
                __half h0 = __float2half_rn(v0), h1 = __float2half_rn(v1);
                __half h2 = __float2half_rn(v2), h3 = __float2half_rn(v3);
                __half l0 = __float2half_rn(v0 - __half2float(h0));
                __half l1 = __float2half_rn(v1 - __half2float(h1));
                __half l2 = __float2half_rn(v2 - __half2float(h2));
                __half l3 = __float2half_rn(v3 - __half2float(h3));
                *(__half2*)&ChH[(size_t)row * 256 + col]       = __halves2half2(h0, h1);
                *(__half2*)&ChL[(size_t)row * 256 + col]       = __halves2half2(l0, l1);
                *(__half2*)&ChH[(size_t)(row + 8) * 256 + col] = __halves2half2(h2, h3);
                *(__half2*)&ChL[(size_t)(row + 8) * 256 + col] = __halves2half2(l2, l3);
            } else {
                Cf[(size_t)row * ldc + col]           = v0;
                Cf[(size_t)row * ldc + col + 1]       = v1;
                Cf[(size_t)(row + 8) * ldc + col]     = v2;
                Cf[(size_t)(row + 8) * ldc + col + 1] = v3;
            }
        }
    }
}

// ---------------- launch -----------------------------------------------------
extern "C" void kernel_launch(void* const* d_in, const int* in_sizes, int n_in,
                              void* d_out, int out_size) {
    const float* pts   = (const float*)d_in[0];
    const float* kp    = (const float*)d_in[1];
    const float* trans = (const float*)d_in[2];
    const int*   nbr   = (const int*)  d_in[3];
    const float* rest  = (const float*)d_in[4];
    const float* lat   = (const float*)d_in[5];
    const float* W1    = (const float*)d_in[6];
    const float* b1    = (const float*)d_in[7];
    const float* W2    = (const float*)d_in[8];
    const float* b2    = (const float*)d_in[9];
    const float* W3    = (const float*)d_in[10];
    const float* b3    = (const float*)d_in[11];
    float*       out   = (float*)d_out;

    void *pFH, *pFL, *p1H, *p1L, *p2H, *p2L;
    void *w1h, *w1l, *w2h, *w2l, *w3h, *w3l;
    cudaGetSymbolAddress(&pFH, g_featH);
    cudaGetSymbolAddress(&pFL, g_featL);
    cudaGetSymbolAddress(&p1H, g_h1H);
    cudaGetSymbolAddress(&p1L, g_h1L);
    cudaGetSymbolAddress(&p2H, g_h2H);
    cudaGetSymbolAddress(&p2L, g_h2L);
    cudaGetSymbolAddress(&w1h, g_W1h);
    cudaGetSymbolAddress(&w1l, g_W1l);
    cudaGetSymbolAddress(&w2h, g_W2h);
    cudaGetSymbolAddress(&w2l, g_W2l);
    cudaGetSymbolAddress(&w3h, g_W3h);
    cudaGetSymbolAddress(&w3l, g_W3l);

    cudaFuncSetAttribute((const void*)gemm_hmma<0>, cudaFuncAttributeMaxDynamicSharedMemorySize, GEMM_SMEM);
    cudaFuncSetAttribute((const void*)gemm_hmma<1>, cudaFuncAttributeMaxDynamicSharedMemorySize, GEMM_SMEM);

    transpose_all<<<dim3(LDF / 32, 8, 3), dim3(32, 8)>>>(
        W1, W2, W3, (__half*)w1h, (__half*)w1l,
        (__half*)w2h, (__half*)w2l, (__half*)w3h, (__half*)w3l);
    invert_kernel<<<(NV + 127) / 128, 128>>>(trans);
    knn_kernel<<<dim3(NPTS / 256, SPLIT), 256>>>(pts, kp);
    feat_kernel<<<NPTS / 8, 256>>>(pts, kp, nbr, rest, lat, out);

    dim3 ggrid(NPTS / 128, 2);
    gemm_hmma<1><<<ggrid, 256, GEMM_SMEM>>>(
        (const __half*)pFH, (const __half*)pFL, LDF,
        (const __half*)w1h, (const __half*)w1l, LDF,
        b1, nullptr, 0, (__half*)p1H, (__half*)p1L, LDF / 32);
    gemm_hmma<1><<<ggrid, 256, GEMM_SMEM>>>(
        (const __half*)p1H, (const __half*)p1L, 256,
        (const __half*)w2h, (const __half*)w2l, 256,
        b2, nullptr, 0, (__half*)p2H, (__half*)p2L, 256 / 32);
    gemm_hmma<0><<<ggrid, 256, GEMM_SMEM>>>(
        (const __half*)p2H, (const __half*)p2L, 256,
        (const __half*)w3h, (const __half*)w3l, 256,
        b3, out, 283, nullptr, nullptr, 256 / 32);
}

// round 8
// speedup vs baseline: 1.9193x; 1.2565x over previous
#include <cuda_runtime.h>
#include <cuda_fp16.h>
#include <cstdint>
#include <math.h>

#define NV      6890
#define NPTS    16384
#define SPLIT   8
#define KRANGE  862      // ceil(6890/8)
#define LDF     704

// ---------------- scratch (device globals) -----------------------------------
__device__ __align__(16) __half  g_featH[(size_t)NPTS * LDF];
__device__ __align__(16) __half  g_h1H[(size_t)NPTS * 256];
__device__ __align__(16) __half  g_h2H[(size_t)NPTS * 256];
__device__ __align__(16) __half  g_W1h[(size_t)256 * LDF];
__device__ __align__(16) __half  g_W1l[(size_t)256 * LDF];
__device__ __align__(16) __half  g_W2h[(size_t)256 * 256];
__device__ __align__(16) __half  g_W2l[(size_t)256 * 256];
__device__ __align__(16) __half  g_W3h[(size_t)256 * 256];
__device__ __align__(16) __half  g_W3l[(size_t)256 * 256];
__device__ float                 g_Rinv[NV * 9];
__device__ unsigned long long    g_part[SPLIT * NPTS];

// ======================= small PTX helpers ===================================
__device__ __forceinline__ uint32_t smem_u32(const void* p) {
    uint32_t a;
    asm("{ .reg .u64 t; cvta.to.shared.u64 t, %1; cvt.u32.u64 %0, t; }" : "=r"(a) : "l"(p));
    return a;
}
__device__ __forceinline__ void cpa16(uint32_t dst, const void* src) {
    asm volatile("cp.async.cg.shared.global [%0], [%1], 16;" :: "r"(dst), "l"(src));
}
#define CPA_COMMIT() asm volatile("cp.async.commit_group;" ::: "memory")

__device__ __forceinline__ void ldm4(uint32_t* r, uint32_t addr) {
    asm volatile("ldmatrix.sync.aligned.m8n8.x4.shared.b16 {%0,%1,%2,%3}, [%4];"
                 : "=r"(r[0]), "=r"(r[1]), "=r"(r[2]), "=r"(r[3]) : "r"(addr));
}
__device__ __forceinline__ void mma16816(float* c, const uint32_t* a, uint32_t b0, uint32_t b1) {
    asm volatile(
        "mma.sync.aligned.m16n8k16.row.col.f32.f16.f16.f32 "
        "{%0,%1,%2,%3}, {%4,%5,%6,%7}, {%8,%9}, {%0,%1,%2,%3};"
        : "+f"(c[0]), "+f"(c[1]), "+f"(c[2]), "+f"(c[3])
        : "r"(a[0]), "r"(a[1]), "r"(a[2]), "r"(a[3]), "r"(b0), "r"(b1));
}

__device__ __forceinline__ void wsplit(__half* H, __half* L, size_t idx, float v) {
    __half h = __float2half_rn(v);
    H[idx] = h;
    L[idx] = __float2half_rn(v - __half2float(h));
}

// ---------------- accurate fp32 sincos (no FP64) -----------------------------
__device__ __forceinline__ void sincos_acc(float x, float* s, float* c) {
    const float C1 = 6.28125f;
    const float C2 = (float)1.9353071795864769e-3;
    const float C3 = (float)(6.283185307179586476925286766559 - 6.28125 -
                             (double)((float)1.9353071795864769e-3));
    float q = rintf(x * 0.15915494309189535f);
    float r = fmaf(q, -C1, x);
    r = fmaf(q, -C2, r);
    r = fmaf(q, -C3, r);
    sincosf(r, s, c);
}

// ---------------- merged weight transpose + split (one launch) ---------------
__global__ void transpose_all(const float* __restrict__ W1, const float* __restrict__ W2,
                              const float* __restrict__ W3,
                              __half* __restrict__ W1h, __half* __restrict__ W1l,
                              __half* __restrict__ W2h, __half* __restrict__ W2l,
                              __half* __restrict__ W3h, __half* __restrict__ W3l) {
    int z = blockIdx.z;
    const float* W; __half *Wh, *Wl; int K, ldk;
    if (z == 0)      { W = W1; Wh = W1h; Wl = W1l; K = 700; ldk = LDF; }
    else if (z == 1) { W = W2; Wh = W2h; Wl = W2l; K = 256; ldk = 256; }
    else             { W = W3; Wh = W3h; Wl = W3l; K = 256; ldk = 256; }
    if (blockIdx.x * 32 >= ldk) return;

    __shared__ float tile[32][33];
    int kb = blockIdx.x * 32;
    int nb = blockIdx.y * 32;
    int tx = threadIdx.x, ty = threadIdx.y;
#pragma unroll
    for (int i = 0; i < 4; i++) {
        int k = kb + ty + i * 8;
        tile[ty + i * 8][tx] = (k < K) ? W[(size_t)k * 256 + nb + tx] : 0.0f;
    }
    __syncthreads();
#pragma unroll
    for (int i = 0; i < 4; i++) {
        int n = nb + ty + i * 8;
        wsplit(Wh, Wl, (size_t)n * ldk + kb + tx, tile[tx][ty + i * 8]);
    }
}

// ---------------- kernel 1: invert 4x4 per vertex ----------------------------
__global__ void invert_kernel(const float* __restrict__ trans) {
    int v = blockIdx.x * blockDim.x + threadIdx.x;
    if (v >= NV) return;
    float m[16];
#pragma unroll
    for (int k = 0; k < 16; k++) m[k] = trans[k * NV + v];

    float i0  =  m[5]*m[10]*m[15] - m[5]*m[11]*m[14] - m[9]*m[6]*m[15] + m[9]*m[7]*m[14] + m[13]*m[6]*m[11] - m[13]*m[7]*m[10];
    float i4  = -m[4]*m[10]*m[15] + m[4]*m[11]*m[14] + m[8]*m[6]*m[15] - m[8]*m[7]*m[14] - m[12]*m[6]*m[11] + m[12]*m[7]*m[10];
    float i8  =  m[4]*m[9]*m[15]  - m[4]*m[11]*m[13] - m[8]*m[5]*m[15] + m[8]*m[7]*m[13] + m[12]*m[5]*m[11] - m[12]*m[7]*m[9];
    float i12 = -m[4]*m[9]*m[14]  + m[4]*m[10]*m[13] + m[8]*m[5]*m[14] - m[8]*m[6]*m[13] - m[12]*m[5]*m[10] + m[12]*m[6]*m[9];
    float i1  = -m[1]*m[10]*m[15] + m[1]*m[11]*m[14] + m[9]*m[2]*m[15] - m[9]*m[3]*m[14] - m[13]*m[2]*m[11] + m[13]*m[3]*m[10];
    float i5  =  m[0]*m[10]*m[15] - m[0]*m[11]*m[14] - m[8]*m[2]*m[15] + m[8]*m[3]*m[14] + m[12]*m[2]*m[11] - m[12]*m[3]*m[10];
    float i9  = -m[0]*m[9]*m[15]  + m[0]*m[11]*m[13] + m[8]*m[1]*m[15] - m[8]*m[3]*m[13] - m[12]*m[1]*m[11] + m[12]*m[3]*m[9];
    float i2  =  m[1]*m[6]*m[15]  - m[1]*m[7]*m[14]  - m[5]*m[2]*m[15] + m[5]*m[3]*m[14] + m[13]*m[2]*m[7]  - m[13]*m[3]*m[6];
    float i6  = -m[0]*m[6]*m[15]  + m[0]*m[7]*m[14]  + m[4]*m[2]*m[15] - m[4]*m[3]*m[14] - m[12]*m[2]*m[7]  + m[12]*m[3]*m[6];
    float i10 =  m[0]*m[5]*m[15]  - m[0]*m[7]*m[13]  - m[4]*m[1]*m[15] + m[4]*m[3]*m[13] + m[12]*m[1]*m[7]  - m[12]*m[3]*m[5];

    float det = m[0]*i0 + m[1]*i4 + m[2]*i8 + m[3]*i12;
    float id  = 1.0f / det;
    float* R = g_Rinv + v * 9;
    R[0] = i0*id;  R[1] = i1*id;  R[2] = i2*id;
    R[3] = i4*id;  R[4] = i5*id;  R[5] = i6*id;
    R[6] = i8*id;  R[7] = i9*id;  R[8] = i10*id;
}

// ---------------- kernel 2: KNN, 8-way keypoint split -------------------------
__global__ __launch_bounds__(256) void knn_kernel(const float* __restrict__ pts,
                                                  const float* __restrict__ kp) {
    __shared__ float4 sk[KRANGE];
    int pt = blockIdx.x * 256 + threadIdx.x;
    int ks = blockIdx.y * KRANGE;
    int ke = min(ks + KRANGE, NV);
    int n  = ke - ks;

    for (int i = threadIdx.x; i < n; i += 256) {
        int vv = ks + i;
        float kx = kp[vv*3], ky = kp[vv*3+1], kz = kp[vv*3+2];
        sk[i] = make_float4(kx, ky, kz, -0.5f*(kx*kx + ky*ky + kz*kz));
    }
    __syncthreads();

    float px = pts[pt*6], py = pts[pt*6+1], pz = pts[pt*6+2];
    float best = -1e30f; int bi = ks;

    int i = 0;
#pragma unroll 1
    for (; i + 4 <= n; i += 4) {
#pragma unroll
        for (int u = 0; u < 4; u++) {
            float4 k = sk[i+u];
            float s = fmaf(px, k.x, fmaf(py, k.y, fmaf(pz, k.z, k.w)));
            if (s > best) { best = s; bi = ks + i + u; }
        }
    }
    for (; i < n; i++) {
        float4 k = sk[i];
        float s = fmaf(px, k.x, fmaf(py, k.y, fmaf(pz, k.z, k.w)));
        if (s > best) { best = s; bi = ks + i; }
    }
    float mneg = -best;
    unsigned int ub = __float_as_uint(mneg);
    ub = (ub & 0x80000000u) ? ~ub : (ub | 0x80000000u);
    g_part[blockIdx.y * NPTS + pt] = ((unsigned long long)ub << 32) | (unsigned int)bi;
}

// ---------------- kernel 3: feature build (fused knn-reduce + recurrence) ----
__global__ __launch_bounds__(256) void feat_kernel(const float* __restrict__ pts,
                                                   const float* __restrict__ kp,
                                                   const int*   __restrict__ nbr,
                                                   const float* __restrict__ rest,
                                                   const float* __restrict__ lat,
                                                   float*       __restrict__ out) {
    int gw   = (blockIdx.x * blockDim.x + threadIdx.x) >> 5;
    int lane = threadIdx.x & 31;
    if (gw >= NPTS) return;

    unsigned long long pv = (lane < SPLIT) ? g_part[(size_t)lane * NPTS + gw] : ~0ull;
    unsigned long long o;
    o = __shfl_xor_sync(0xffffffffu, pv, 1); if (o < pv) pv = o;
    o = __shfl_xor_sync(0xffffffffu, pv, 2); if (o < pv) pv = o;
    o = __shfl_xor_sync(0xffffffffu, pv, 4); if (o < pv) pv = o;
    int kidx = (int)(__shfl_sync(0xffffffffu, pv, 0) & 0xFFFFFFFFull);

    float px = pts[gw*6], py = pts[gw*6+1], pz = pts[gw*6+2];

    int vj = (lane < 7) ? nbr[kidx*7 + lane] : 0;
    int j  = (lane < 21) ? (lane / 3) : ((lane < 28) ? (lane - 21) : 0);
    int v  = __shfl_sync(0xffffffffu, vj, j);

    float vf = 0.0f;
    if (lane < 21) {
        vf = rest[v*3 + (lane % 3)];
    } else if (lane < 28) {
        float dx = px - kp[v*3], dy = py - kp[v*3+1], dz = pz - kp[v*3+2];
        vf = sqrtf(dx*dx + dy*dy + dz*dz);
    }

    size_t base = (size_t)gw * LDF;
    if (lane < 28) {
        g_featH[base + lane] = __float2half_rn(vf);
        float s, c;
        sincos_acc(vf, &s, &c);
#pragma unroll
        for (int k = 0; k < 10; k++) {
            g_featH[base + 28  + k*28 + lane] = __float2half_rn(s);
            g_featH[base + 308 + k*28 + lane] = __float2half_rn(c);
            float sn = 2.0f * s * c;
            float cn = fmaf(-2.0f * s, s, 1.0f);
            s = sn; c = cn;
        }
    }
    if (lane < 4) g_featH[base + 700 + lane] = __float2half_rn(0.0f);

#pragma unroll
    for (int it = 0; it < 4; it++) {
        int l  = it * 32 + lane;
        int jj = (l < 112) ? (l >> 4) : 0;
        int vv = __shfl_sync(0xffffffffu, vj, jj);
        if (l < 112) g_featH[base + 588 + l] = __float2half_rn(lat[vv*16 + (l & 15)]);
    }

    if (lane == 0) {
        float dx = px - kp[kidx*3], dy = py - kp[kidx*3+1], dz = pz - kp[kidx*3+2];
        const float* R = g_Rinv + kidx * 9;
        float d0 = R[0]*dx + R[1]*dy + R[2]*dz;
        float d1 = R[3]*dx + R[4]*dy + R[5]*dz;
        float d2 = R[6]*dx + R[7]*dy + R[8]*dz;
        float nn = sqrtf(d0*d0 + d1*d1 + d2*d2);
        float iv = 1.0f / fmaxf(nn, 1e-12f);
        d0 *= iv; d1 *= iv; d2 *= iv;
        float* op = out + (size_t)gw * 283 + 256;
        op[0] = d0; op[1] = d1; op[2] = d2;
        float dir[3] = {d0, d1, d2};
#pragma unroll
        for (int c = 0; c < 3; c++) {
            float s, cc;
            sincos_acc(dir[c], &s, &cc);
#pragma unroll
            for (int k = 0; k < 4; k++) {
                op[3  + k*3 + c] = s;
                op[15 + k*3 + c] = cc;
                float sn = 2.0f * s * cc;
                float cn = fmaf(-2.0f * s, s, 1.0f);
                s = sn; cc = cn;
            }
        }
    }
}

// ---------------- kernel 4: fp16 2-term split HMMA GEMM ----------------------
// C = act(A_hi @ (B_hi + B_lo)^T + bias). A is plain fp16; B split hi/lo.
#define PADH   40
#define TILEB  (128 * PADH * 2)            // 10240 B per tile
#define BUFB   (3 * TILEB)                 // Ah, Bh, Bl
#define GEMM_SMEM (2 * BUFB)               // 61440 B

template <int OUTMODE>  // 0: fp32 out, no relu; 1: relu + fp16 out
__global__ __launch_bounds__(256, 2) void gemm_hmma(
    const __half* __restrict__ Ah, int lda,
    const __half* __restrict__ Bh, const __half* __restrict__ Bl, int ldb,
    const float* __restrict__ bias,
    float* __restrict__ Cf, int ldc,
    __half* __restrict__ CH,
    int kchunks)
{
    extern __shared__ char sm[];
    const int tid  = threadIdx.x;
    const int wid  = tid >> 5, lane = tid & 31;
    const int g    = lane >> 2, t = lane & 3;
    const int m0   = blockIdx.x * 128, n0 = blockIdx.y * 128;
    const int m0w  = (wid >> 1) * 32, n0w = (wid & 1) * 64;

    float acc[2][8][4];
#pragma unroll
    for (int mi = 0; mi < 2; mi++)
#pragma unroll
        for (int ni = 0; ni < 8; ni++)
#pragma unroll
            for (int q = 0; q < 4; q++) acc[mi][ni][q] = 0.0f;

    auto issue = [&](int ch, int buf) {
        const int k0 = ch * 32;
        char* base = sm + buf * BUFB;
#pragma unroll
        for (int i = 0; i < 2; i++) {
            int s = tid + i * 256;
            int r = s >> 2, c = (s & 3) * 8;
            uint32_t off = (uint32_t)(r * PADH + c) * 2;
            cpa16(smem_u32(base)             + off, Ah + (size_t)(m0 + r) * lda + k0 + c);
            cpa16(smem_u32(base + TILEB)     + off, Bh + (size_t)(n0 + r) * ldb + k0 + c);
            cpa16(smem_u32(base + 2 * TILEB) + off, Bl + (size_t)(n0 + r) * ldb + k0 + c);
        }
        CPA_COMMIT();
    };

    issue(0, 0);

    for (int ch = 0; ch < kchunks; ch++) {
        if (ch + 1 < kchunks) {
            issue(ch + 1, (ch + 1) & 1);
            asm volatile("cp.async.wait_group 1;" ::: "memory");
        } else {
            asm volatile("cp.async.wait_group 0;" ::: "memory");
        }
        __syncthreads();

        char* base = sm + (ch & 1) * BUFB;
        uint32_t sAh = smem_u32(base);
        uint32_t sBh = sAh + TILEB;
        uint32_t sBl = sAh + 2 * TILEB;

        const int arow = lane & 15;
        const int asel = (lane >> 4) << 3;
        const int brow = (lane & 7) + ((lane & 16) ? 8 : 0);
        const int bsel = (lane & 8) ? 8 : 0;

#pragma unroll
        for (int ks = 0; ks < 2; ks++) {
            const int kc = ks * 16;
            uint32_t ah[2][4];
#pragma unroll
            for (int mi = 0; mi < 2; mi++) {
                uint32_t off = (uint32_t)((m0w + mi * 16 + arow) * PADH + kc + asel) * 2;
                ldm4(ah[mi], sAh + off);
            }
#pragma unroll
            for (int ph = 0; ph < 2; ph++) {
                uint32_t bh[2][4], bl[2][4];
#pragma unroll
                for (int pp = 0; pp < 2; pp++) {
                    int p = ph * 2 + pp;
                    uint32_t off = (uint32_t)((n0w + p * 16 + brow) * PADH + kc + bsel) * 2;
                    ldm4(bh[pp], sBh + off);
                    ldm4(bl[pp], sBl + off);
                }
                // term 0: hi*hi
#pragma unroll
                for (int pp = 0; pp < 2; pp++)
#pragma unroll
                    for (int q = 0; q < 2; q++)
#pragma unroll
                        for (int mi = 0; mi < 2; mi++)
                            mma16816(acc[mi][(ph*2+pp)*2+q], ah[mi], bh[pp][q*2], bh[pp][q*2+1]);
                // term 1: hi*lo
#pragma unroll
                for (int pp = 0; pp < 2; pp++)
#pragma unroll
                    for (int q = 0; q < 2; q++)
#pragma unroll
                        for (int mi = 0; mi < 2; mi++)
                            mma16816(acc[mi][(ph*2+pp)*2+q], ah[mi], bl[pp][q*2], bl[pp][q*2+1]);
            }
        }
        __syncthreads();
    }

#pragma unroll
    for (int mi = 0; mi < 2; mi++) {
        int row = m0 + m0w + mi * 16 + g;
#pragma unroll
        for (int ni = 0; ni < 8; ni++) {
            int col = n0 + n0w + ni * 8 + 2 * t;
            float b0 = bias[col], b1 = bias[col + 1];
            float v0 = acc[mi][ni][0] + b0;
            float v1 = acc[mi][ni][1] + b1;
            float v2 = acc[mi][ni][2] + b0;
            float v3 = acc[mi][ni][3] + b1;
            if (OUTMODE == 1) {
                v0 = fmaxf(v0, 0.f); v1 = fmaxf(v1, 0.f);
                v2 = fmaxf(v2, 0.f); v3 = fmaxf(v3, 0.f);
                *(__half2*)&CH[(size_t)row * 256 + col] =
                    __halves2half2(__float2half_rn(v0), __float2half_rn(v1));
                *(__half2*)&CH[(size_t)(row + 8) * 256 + col] =
                    __halves2half2(__float2half_rn(v2), __float2half_rn(v3));
            } else {
                Cf[(size_t)row * ldc + col]           = v0;
                Cf[(size_t)row * ldc + col + 1]       = v1;
                Cf[(size_t)(row + 8) * ldc + col]     = v2;
                Cf[(size_t)(row + 8) * ldc + col + 1] = v3;
            }
        }
    }
}

// ---------------- launch -----------------------------------------------------
extern "C" void kernel_launch(void* const* d_in, const int* in_sizes, int n_in,
                              void* d_out, int out_size) {
    const float* pts   = (const float*)d_in[0];
    const float* kp    = (const float*)d_in[1];
    const float* trans = (const float*)d_in[2];
    const int*   nbr   = (const int*)  d_in[3];
    const float* rest  = (const float*)d_in[4];
    const float* lat   = (const float*)d_in[5];
    const float* W1    = (const float*)d_in[6];
    const float* b1    = (const float*)d_in[7];
    const float* W2    = (const float*)d_in[8];
    const float* b2    = (const float*)d_in[9];
    const float* W3    = (const float*)d_in[10];
    const float* b3    = (const float*)d_in[11];
    float*       out   = (float*)d_out;

    void *pFH, *p1H, *p2H;
    void *w1h, *w1l, *w2h, *w2l, *w3h, *w3l;
    cudaGetSymbolAddress(&pFH, g_featH);
    cudaGetSymbolAddress(&p1H, g_h1H);
    cudaGetSymbolAddress(&p2H, g_h2H);
    cudaGetSymbolAddress(&w1h, g_W1h);
    cudaGetSymbolAddress(&w1l, g_W1l);
    cudaGetSymbolAddress(&w2h, g_W2h);
    cudaGetSymbolAddress(&w2l, g_W2l);
    cudaGetSymbolAddress(&w3h, g_W3h);
    cudaGetSymbolAddress(&w3l, g_W3l);

    cudaFuncSetAttribute((const void*)gemm_hmma<0>, cudaFuncAttributeMaxDynamicSharedMemorySize, GEMM_SMEM);
    cudaFuncSetAttribute((const void*)gemm_hmma<1>, cudaFuncAttributeMaxDynamicSharedMemorySize, GEMM_SMEM);

    transpose_all<<<dim3(LDF / 32, 8, 3), dim3(32, 8)>>>(
        W1, W2, W3, (__half*)w1h, (__half*)w1l,
        (__half*)w2h, (__half*)w2l, (__half*)w3h, (__half*)w3l);
    invert_kernel<<<(NV + 127) / 128, 128>>>(trans);
    knn_kernel<<<dim3(NPTS / 256, SPLIT), 256>>>(pts, kp);
    feat_kernel<<<NPTS / 8, 256>>>(pts, kp, nbr, rest, lat, out);

    dim3 ggrid(NPTS / 128, 2);
    gemm_hmma<1><<<ggrid, 256, GEMM_SMEM>>>(
        (const __half*)pFH, LDF,
        (const __half*)w1h, (const __half*)w1l, LDF,
        b1, nullptr, 0, (__half*)p1H, LDF / 32);
    gemm_hmma<1><<<ggrid, 256, GEMM_SMEM>>>(
        (const __half*)p1H, 256,
        (const __half*)w2h, (const __half*)w2l, 256,
        b2, nullptr, 0, (__half*)p2H, 256 / 32);
    gemm_hmma<0><<<ggrid, 256, GEMM_SMEM>>>(
        (const __half*)p2H, 256,
        (const __half*)w3h, (const __half*)w3l, 256,
        b3, out, 283, nullptr, 256 / 32);
}

// round 9
// speedup vs baseline: 2.3814x; 1.2408x over previous
#include <cuda_runtime.h>
#include <cuda_fp16.h>
#include <cstdint>
#include <math.h>

#define NV      6890
#define NPTS    16384
#define SPLIT   8
#define KRANGE  862      // ceil(6890/8)
#define LDF     704

// ---------------- scratch (device globals) -----------------------------------
__device__ __align__(16) __half  g_featH[(size_t)NPTS * LDF];
__device__ __align__(16) __half  g_h1H[(size_t)NPTS * 256];
__device__ __align__(16) __half  g_h2H[(size_t)NPTS * 256];
__device__ __align__(16) __half  g_W1h[(size_t)256 * LDF];
__device__ __align__(16) __half  g_W2h[(size_t)256 * 256];
__device__ __align__(16) __half  g_W3h[(size_t)256 * 256];
__device__ float                 g_Rinv[NV * 9];
__device__ unsigned long long    g_part[SPLIT * NPTS];

// ======================= small PTX helpers ===================================
__device__ __forceinline__ uint32_t smem_u32(const void* p) {
    uint32_t a;
    asm("{ .reg .u64 t; cvta.to.shared.u64 t, %1; cvt.u32.u64 %0, t; }" : "=r"(a) : "l"(p));
    return a;
}
__device__ __forceinline__ void cpa16(uint32_t dst, const void* src) {
    asm volatile("cp.async.cg.shared.global [%0], [%1], 16;" :: "r"(dst), "l"(src));
}
#define CPA_COMMIT() asm volatile("cp.async.commit_group;" ::: "memory")

__device__ __forceinline__ void ldm4(uint32_t* r, uint32_t addr) {
    asm volatile("ldmatrix.sync.aligned.m8n8.x4.shared.b16 {%0,%1,%2,%3}, [%4];"
                 : "=r"(r[0]), "=r"(r[1]), "=r"(r[2]), "=r"(r[3]) : "r"(addr));
}
__device__ __forceinline__ void mma16816(float* c, const uint32_t* a, uint32_t b0, uint32_t b1) {
    asm volatile(
        "mma.sync.aligned.m16n8k16.row.col.f32.f16.f16.f32 "
        "{%0,%1,%2,%3}, {%4,%5,%6,%7}, {%8,%9}, {%0,%1,%2,%3};"
        : "+f"(c[0]), "+f"(c[1]), "+f"(c[2]), "+f"(c[3])
        : "r"(a[0]), "r"(a[1]), "r"(a[2]), "r"(a[3]), "r"(b0), "r"(b1));
}

// ---------------- accurate fp32 sincos (no FP64) -----------------------------
__device__ __forceinline__ void sincos_acc(float x, float* s, float* c) {
    const float C1 = 6.28125f;
    const float C2 = (float)1.9353071795864769e-3;
    const float C3 = (float)(6.283185307179586476925286766559 - 6.28125 -
                             (double)((float)1.9353071795864769e-3));
    float q = rintf(x * 0.15915494309189535f);
    float r = fmaf(q, -C1, x);
    r = fmaf(q, -C2, r);
    r = fmaf(q, -C3, r);
    sincosf(r, s, c);
}

// ---------------- merged weight transpose (one launch, fp16 out) -------------
__global__ void transpose_all(const float* __restrict__ W1, const float* __restrict__ W2,
                              const float* __restrict__ W3,
                              __half* __restrict__ W1h, __half* __restrict__ W2h,
                              __half* __restrict__ W3h) {
    int z = blockIdx.z;
    const float* W; __half* Wh; int K, ldk;
    if (z == 0)      { W = W1; Wh = W1h; K = 700; ldk = LDF; }
    else if (z == 1) { W = W2; Wh = W2h; K = 256; ldk = 256; }
    else             { W = W3; Wh = W3h; K = 256; ldk = 256; }
    if (blockIdx.x * 32 >= ldk) return;

    __shared__ float tile[32][33];
    int kb = blockIdx.x * 32;
    int nb = blockIdx.y * 32;
    int tx = threadIdx.x, ty = threadIdx.y;
#pragma unroll
    for (int i = 0; i < 4; i++) {
        int k = kb + ty + i * 8;
        tile[ty + i * 8][tx] = (k < K) ? W[(size_t)k * 256 + nb + tx] : 0.0f;
    }
    __syncthreads();
#pragma unroll
    for (int i = 0; i < 4; i++) {
        int n = nb + ty + i * 8;
        Wh[(size_t)n * ldk + kb + tx] = __float2half_rn(tile[tx][ty + i * 8]);
    }
}

// ---------------- kernel 1: invert 4x4 per vertex ----------------------------
__global__ void invert_kernel(const float* __restrict__ trans) {
    int v = blockIdx.x * blockDim.x + threadIdx.x;
    if (v >= NV) return;
    float m[16];
#pragma unroll
    for (int k = 0; k < 16; k++) m[k] = trans[k * NV + v];

    float i0  =  m[5]*m[10]*m[15] - m[5]*m[11]*m[14] - m[9]*m[6]*m[15] + m[9]*m[7]*m[14] + m[13]*m[6]*m[11] - m[13]*m[7]*m[10];
    float i4  = -m[4]*m[10]*m[15] + m[4]*m[11]*m[14] + m[8]*m[6]*m[15] - m[8]*m[7]*m[14] - m[12]*m[6]*m[11] + m[12]*m[7]*m[10];
    float i8  =  m[4]*m[9]*m[15]  - m[4]*m[11]*m[13] - m[8]*m[5]*m[15] + m[8]*m[7]*m[13] + m[12]*m[5]*m[11] - m[12]*m[7]*m[9];
    float i12 = -m[4]*m[9]*m[14]  + m[4]*m[10]*m[13] + m[8]*m[5]*m[14] - m[8]*m[6]*m[13] - m[12]*m[5]*m[10] + m[12]*m[6]*m[9];
    float i1  = -m[1]*m[10]*m[15] + m[1]*m[11]*m[14] + m[9]*m[2]*m[15] - m[9]*m[3]*m[14] - m[13]*m[2]*m[11] + m[13]*m[3]*m[10];
    float i5  =  m[0]*m[10]*m[15] - m[0]*m[11]*m[14] - m[8]*m[2]*m[15] + m[8]*m[3]*m[14] + m[12]*m[2]*m[11] - m[12]*m[3]*m[10];
    float i9  = -m[0]*m[9]*m[15]  + m[0]*m[11]*m[13] + m[8]*m[1]*m[15] - m[8]*m[3]*m[13] - m[12]*m[1]*m[11] + m[12]*m[3]*m[9];
    float i2  =  m[1]*m[6]*m[15]  - m[1]*m[7]*m[14]  - m[5]*m[2]*m[15] + m[5]*m[3]*m[14] + m[13]*m[2]*m[7]  - m[13]*m[3]*m[6];
    float i6  = -m[0]*m[6]*m[15]  + m[0]*m[7]*m[14]  + m[4]*m[2]*m[15] - m[4]*m[3]*m[14] - m[12]*m[2]*m[7]  + m[12]*m[3]*m[6];
    float i10 =  m[0]*m[5]*m[15]  - m[0]*m[7]*m[13]  - m[4]*m[1]*m[15] + m[4]*m[3]*m[13] + m[12]*m[1]*m[7]  - m[12]*m[3]*m[5];

    float det = m[0]*i0 + m[1]*i4 + m[2]*i8 + m[3]*i12;
    float id  = 1.0f / det;
    float* R = g_Rinv + v * 9;
    R[0] = i0*id;  R[1] = i1*id;  R[2] = i2*id;
    R[3] = i4*id;  R[4] = i5*id;  R[5] = i6*id;
    R[6] = i8*id;  R[7] = i9*id;  R[8] = i10*id;
}

// ---------------- kernel 2: KNN, 8-way split, dual compare chains -------------
__global__ __launch_bounds__(256) void knn_kernel(const float* __restrict__ pts,
                                                  const float* __restrict__ kp) {
    __shared__ float4 sk[KRANGE];
    int pt = blockIdx.x * 256 + threadIdx.x;
    int ks = blockIdx.y * KRANGE;
    int ke = min(ks + KRANGE, NV);
    int n  = ke - ks;

    for (int i = threadIdx.x; i < n; i += 256) {
        int vv = ks + i;
        float kx = kp[vv*3], ky = kp[vv*3+1], kz = kp[vv*3+2];
        sk[i] = make_float4(kx, ky, kz, -0.5f*(kx*kx + ky*ky + kz*kz));
    }
    __syncthreads();

    float px = pts[pt*6], py = pts[pt*6+1], pz = pts[pt*6+2];
    // two independent chains (even/odd) to halve RAW dependency depth
    float b0 = -1e30f, b1 = -1e30f;
    int   i0 = ks, i1 = ks;

    int i = 0;
#pragma unroll 1
    for (; i + 4 <= n; i += 4) {
#pragma unroll
        for (int u = 0; u < 4; u += 2) {
            float4 k0 = sk[i+u];
            float4 k1 = sk[i+u+1];
            float s0 = fmaf(px, k0.x, fmaf(py, k0.y, fmaf(pz, k0.z, k0.w)));
            float s1 = fmaf(px, k1.x, fmaf(py, k1.y, fmaf(pz, k1.z, k1.w)));
            if (s0 > b0) { b0 = s0; i0 = ks + i + u; }
            if (s1 > b1) { b1 = s1; i1 = ks + i + u + 1; }
        }
    }
    for (; i < n; i++) {
        float4 k = sk[i];
        float s = fmaf(px, k.x, fmaf(py, k.y, fmaf(pz, k.z, k.w)));
        if (s > b0) { b0 = s; i0 = ks + i; }
    }

    // pack (minimize flip(-score) then index; ties -> lowest index)
    auto pack = [](float sc, int idx) {
        unsigned int ub = __float_as_uint(-sc);
        ub = (ub & 0x80000000u) ? ~ub : (ub | 0x80000000u);
        return ((unsigned long long)ub << 32) | (unsigned int)idx;
    };
    unsigned long long p0 = pack(b0, i0), p1 = pack(b1, i1);
    g_part[blockIdx.y * NPTS + pt] = p0 < p1 ? p0 : p1;
}

// ---------------- kernel 3: feature build (fused knn-reduce + recurrence) ----
__global__ __launch_bounds__(256) void feat_kernel(const float* __restrict__ pts,
                                                   const float* __restrict__ kp,
                                                   const int*   __restrict__ nbr,
                                                   const float* __restrict__ rest,
                                                   const float* __restrict__ lat,
                                                   float*       __restrict__ out) {
    int gw   = (blockIdx.x * blockDim.x + threadIdx.x) >> 5;
    int lane = threadIdx.x & 31;
    if (gw >= NPTS) return;

    unsigned long long pv = (lane < SPLIT) ? g_part[(size_t)lane * NPTS + gw] : ~0ull;
    unsigned long long o;
    o = __shfl_xor_sync(0xffffffffu, pv, 1); if (o < pv) pv = o;
    o = __shfl_xor_sync(0xffffffffu, pv, 2); if (o < pv) pv = o;
    o = __shfl_xor_sync(0xffffffffu, pv, 4); if (o < pv) pv = o;
    int kidx = (int)(__shfl_sync(0xffffffffu, pv, 0) & 0xFFFFFFFFull);

    float px = pts[gw*6], py = pts[gw*6+1], pz = pts[gw*6+2];

    int vj = (lane < 7) ? nbr[kidx*7 + lane] : 0;
    int j  = (lane < 21) ? (lane / 3) : ((lane < 28) ? (lane - 21) : 0);
    int v  = __shfl_sync(0xffffffffu, vj, j);

    float vf = 0.0f;
    if (lane < 21) {
        vf = rest[v*3 + (lane % 3)];
    } else if (lane < 28) {
        float dx = px - kp[v*3], dy = py - kp[v*3+1], dz = pz - kp[v*3+2];
        vf = sqrtf(dx*dx + dy*dy + dz*dz);
    }

    size_t base = (size_t)gw * LDF;
    if (lane < 28) {
        g_featH[base + lane] = __float2half_rn(vf);
        float s, c;
        sincos_acc(vf, &s, &c);
#pragma unroll
        for (int k = 0; k < 10; k++) {
            g_featH[base + 28  + k*28 + lane] = __float2half_rn(s);
            g_featH[base + 308 + k*28 + lane] = __float2half_rn(c);
            float sn = 2.0f * s * c;
            float cn = fmaf(-2.0f * s, s, 1.0f);
            s = sn; c = cn;
        }
    }
    if (lane < 4) g_featH[base + 700 + lane] = __float2half_rn(0.0f);

#pragma unroll
    for (int it = 0; it < 4; it++) {
        int l  = it * 32 + lane;
        int jj = (l < 112) ? (l >> 4) : 0;
        int vv = __shfl_sync(0xffffffffu, vj, jj);
        if (l < 112) g_featH[base + 588 + l] = __float2half_rn(lat[vv*16 + (l & 15)]);
    }

    if (lane == 0) {
        float dx = px - kp[kidx*3], dy = py - kp[kidx*3+1], dz = pz - kp[kidx*3+2];
        const float* R = g_Rinv + kidx * 9;
        float d0 = R[0]*dx + R[1]*dy + R[2]*dz;
        float d1 = R[3]*dx + R[4]*dy + R[5]*dz;
        float d2 = R[6]*dx + R[7]*dy + R[8]*dz;
        float nn = sqrtf(d0*d0 + d1*d1 + d2*d2);
        float iv = 1.0f / fmaxf(nn, 1e-12f);
        d0 *= iv; d1 *= iv; d2 *= iv;
        float* op = out + (size_t)gw * 283 + 256;
        op[0] = d0; op[1] = d1; op[2] = d2;
        float dir[3] = {d0, d1, d2};
#pragma unroll
        for (int c = 0; c < 3; c++) {
            float s, cc;
            sincos_acc(dir[c], &s, &cc);
#pragma unroll
            for (int k = 0; k < 4; k++) {
                op[3  + k*3 + c] = s;
                op[15 + k*3 + c] = cc;
                float sn = 2.0f * s * cc;
                float cn = fmaf(-2.0f * s, s, 1.0f);
                s = sn; cc = cn;
            }
        }
    }
}

// ---------------- kernel 4: plain fp16 HMMA GEMM ------------------------------
// C = act(A @ B^T + bias), all-fp16 operands, fp32 accumulate.
#define PADH   40
#define TILEB  (128 * PADH * 2)            // 10240 B per tile
#define BUFB   (2 * TILEB)                 // Ah, Bh
#define GEMM_SMEM (2 * BUFB)               // 40960 B

template <int OUTMODE>  // 0: fp32 out, no relu; 1: relu + fp16 out
__global__ __launch_bounds__(256, 2) void gemm_hmma(
    const __half* __restrict__ Ah, int lda,
    const __half* __restrict__ Bh, int ldb,
    const float* __restrict__ bias,
    float* __restrict__ Cf, int ldc,
    __half* __restrict__ CH,
    int kchunks)
{
    extern __shared__ char sm[];
    const int tid  = threadIdx.x;
    const int wid  = tid >> 5, lane = tid & 31;
    const int g    = lane >> 2, t = lane & 3;
    const int m0   = blockIdx.x * 128, n0 = blockIdx.y * 128;
    const int m0w  = (wid >> 1) * 32, n0w = (wid & 1) * 64;

    float acc[2][8][4];
#pragma unroll
    for (int mi = 0; mi < 2; mi++)
#pragma unroll
        for (int ni = 0; ni < 8; ni++)
#pragma unroll
            for (int q = 0; q < 4; q++) acc[mi][ni][q] = 0.0f;

    auto issue = [&](int ch, int buf) {
        const int k0 = ch * 32;
        char* base = sm + buf * BUFB;
#pragma unroll
        for (int i = 0; i < 2; i++) {
            int s = tid + i * 256;
            int r = s >> 2, c = (s & 3) * 8;
            uint32_t off = (uint32_t)(r * PADH + c) * 2;
            cpa16(smem_u32(base)         + off, Ah + (size_t)(m0 + r) * lda + k0 + c);
            cpa16(smem_u32(base + TILEB) + off, Bh + (size_t)(n0 + r) * ldb + k0 + c);
        }
        CPA_COMMIT();
    };

    issue(0, 0);

    for (int ch = 0; ch < kchunks; ch++) {
        if (ch + 1 < kchunks) {
            issue(ch + 1, (ch + 1) & 1);
            asm volatile("cp.async.wait_group 1;" ::: "memory");
        } else {
            asm volatile("cp.async.wait_group 0;" ::: "memory");
        }
        __syncthreads();

        char* base = sm + (ch & 1) * BUFB;
        uint32_t sAh = smem_u32(base);
        uint32_t sBh = sAh + TILEB;

        const int arow = lane & 15;
        const int asel = (lane >> 4) << 3;
        const int brow = (lane & 7) + ((lane & 16) ? 8 : 0);
        const int bsel = (lane & 8) ? 8 : 0;

#pragma unroll
        for (int ks = 0; ks < 2; ks++) {
            const int kc = ks * 16;
            uint32_t ah[2][4];
#pragma unroll
            for (int mi = 0; mi < 2; mi++) {
                uint32_t off = (uint32_t)((m0w + mi * 16 + arow) * PADH + kc + asel) * 2;
                ldm4(ah[mi], sAh + off);
            }
#pragma unroll
            for (int ph = 0; ph < 2; ph++) {
                uint32_t bh[2][4];
#pragma unroll
                for (int pp = 0; pp < 2; pp++) {
                    int p = ph * 2 + pp;
                    uint32_t off = (uint32_t)((n0w + p * 16 + brow) * PADH + kc + bsel) * 2;
                    ldm4(bh[pp], sBh + off);
                }
#pragma unroll
                for (int pp = 0; pp < 2; pp++)
#pragma unroll
                    for (int q = 0; q < 2; q++)
#pragma unroll
                        for (int mi = 0; mi < 2; mi++)
                            mma16816(acc[mi][(ph*2+pp)*2+q], ah[mi], bh[pp][q*2], bh[pp][q*2+1]);
            }
        }
        __syncthreads();
    }

#pragma unroll
    for (int mi = 0; mi < 2; mi++) {
        int row = m0 + m0w + mi * 16 + g;
#pragma unroll
        for (int ni = 0; ni < 8; ni++) {
            int col = n0 + n0w + ni * 8 + 2 * t;
            float b0 = bias[col], b1 = bias[col + 1];
            float v0 = acc[mi][ni][0] + b0;
            float v1 = acc[mi][ni][1] + b1;
            float v2 = acc[mi][ni][2] + b0;
            float v3 = acc[mi][ni][3] + b1;
            if (OUTMODE == 1) {
                v0 = fmaxf(v0, 0.f); v1 = fmaxf(v1, 0.f);
                v2 = fmaxf(v2, 0.f); v3 = fmaxf(v3, 0.f);
                *(__half2*)&CH[(size_t)row * 256 + col] =
                    __halves2half2(__float2half_rn(v0), __float2half_rn(v1));
                *(__half2*)&CH[(size_t)(row + 8) * 256 + col] =
                    __halves2half2(__float2half_rn(v2), __float2half_rn(v3));
            } else {
                Cf[(size_t)row * ldc + col]           = v0;
                Cf[(size_t)row * ldc + col + 1]       = v1;
                Cf[(size_t)(row + 8) * ldc + col]     = v2;
                Cf[(size_t)(row + 8) * ldc + col + 1] = v3;
            }
        }
    }
}

// ---------------- launch -----------------------------------------------------
extern "C" void kernel_launch(void* const* d_in, const int* in_sizes, int n_in,
                              void* d_out, int out_size) {
    const float* pts   = (const float*)d_in[0];
    const float* kp    = (const float*)d_in[1];
    const float* trans = (const float*)d_in[2];
    const int*   nbr   = (const int*)  d_in[3];
    const float* rest  = (const float*)d_in[4];
    const float* lat   = (const float*)d_in[5];
    const float* W1    = (const float*)d_in[6];
    const float* b1    = (const float*)d_in[7];
    const float* W2    = (const float*)d_in[8];
    const float* b2    = (const float*)d_in[9];
    const float* W3    = (const float*)d_in[10];
    const float* b3    = (const float*)d_in[11];
    float*       out   = (float*)d_out;

    void *pFH, *p1H, *p2H, *w1h, *w2h, *w3h;
    cudaGetSymbolAddress(&pFH, g_featH);
    cudaGetSymbolAddress(&p1H, g_h1H);
    cudaGetSymbolAddress(&p2H, g_h2H);
    cudaGetSymbolAddress(&w1h, g_W1h);
    cudaGetSymbolAddress(&w2h, g_W2h);
    cudaGetSymbolAddress(&w3h, g_W3h);

    cudaFuncSetAttribute((const void*)gemm_hmma<0>, cudaFuncAttributeMaxDynamicSharedMemorySize, GEMM_SMEM);
    cudaFuncSetAttribute((const void*)gemm_hmma<1>, cudaFuncAttributeMaxDynamicSharedMemorySize, GEMM_SMEM);

    transpose_all<<<dim3(LDF / 32, 8, 3), dim3(32, 8)>>>(
        W1, W2, W3, (__half*)w1h, (__half*)w2h, (__half*)w3h);
    invert_kernel<<<(NV + 127) / 128, 128>>>(trans);
    knn_kernel<<<dim3(NPTS / 256, SPLIT), 256>>>(pts, kp);
    feat_kernel<<<NPTS / 8, 256>>>(pts, kp, nbr, rest, lat, out);

    dim3 ggrid(NPTS / 128, 2);
    gemm_hmma<1><<<ggrid, 256, GEMM_SMEM>>>(
        (const __half*)pFH, LDF, (const __half*)w1h, LDF,
        b1, nullptr, 0, (__half*)p1H, LDF / 32);
    gemm_hmma<1><<<ggrid, 256, GEMM_SMEM>>>(
        (const __half*)p1H, 256, (const __half*)w2h, 256,
        b2, nullptr, 0, (__half*)p2H, 256 / 32);
    gemm_hmma<0><<<ggrid, 256, GEMM_SMEM>>>(
        (const __half*)p2H, 256, (const __half*)w3h, 256,
        b3, out, 283, nullptr, 256 / 32);
}

// round 10
// speedup vs baseline: 2.4097x; 1.0119x over previous
#include <cuda_runtime.h>
#include <cuda_fp16.h>
#include <cstdint>
#include <math.h>

#define NV      6890
#define NPTS    16384
#define SPLIT   8
#define KRANGE  862      // ceil(6890/8)
#define LDF     704

// ---------------- scratch (device globals) -----------------------------------
__device__ __align__(16) __half  g_featH[(size_t)NPTS * LDF];
__device__ __align__(16) __half  g_W1h[(size_t)256 * LDF];
__device__ __align__(16) __half  g_W2h[(size_t)256 * 256];
__device__ __align__(16) __half  g_W3h[(size_t)256 * 256];
__device__ float                 g_Rinv[NV * 9];
__device__ unsigned long long    g_part[SPLIT * NPTS];

// ======================= small PTX helpers ===================================
__device__ __forceinline__ uint32_t smem_u32(const void* p) {
    uint32_t a;
    asm("{ .reg .u64 t; cvta.to.shared.u64 t, %1; cvt.u32.u64 %0, t; }" : "=r"(a) : "l"(p));
    return a;
}
__device__ __forceinline__ void cpa16(uint32_t dst, const void* src) {
    asm volatile("cp.async.cg.shared.global [%0], [%1], 16;" :: "r"(dst), "l"(src));
}
#define CPA_COMMIT() asm volatile("cp.async.commit_group;" ::: "memory")

__device__ __forceinline__ void ldm4(uint32_t* r, uint32_t addr) {
    asm volatile("ldmatrix.sync.aligned.m8n8.x4.shared.b16 {%0,%1,%2,%3}, [%4];"
                 : "=r"(r[0]), "=r"(r[1]), "=r"(r[2]), "=r"(r[3]) : "r"(addr));
}
__device__ __forceinline__ void mma16816(float* c, const uint32_t* a, uint32_t b0, uint32_t b1) {
    asm volatile(
        "mma.sync.aligned.m16n8k16.row.col.f32.f16.f16.f32 "
        "{%0,%1,%2,%3}, {%4,%5,%6,%7}, {%8,%9}, {%0,%1,%2,%3};"
        : "+f"(c[0]), "+f"(c[1]), "+f"(c[2]), "+f"(c[3])
        : "r"(a[0]), "r"(a[1]), "r"(a[2]), "r"(a[3]), "r"(b0), "r"(b1));
}

// ---------------- accurate fp32 sincos (no FP64) -----------------------------
__device__ __forceinline__ void sincos_acc(float x, float* s, float* c) {
    const float C1 = 6.28125f;
    const float C2 = (float)1.9353071795864769e-3;
    const float C3 = (float)(6.283185307179586476925286766559 - 6.28125 -
                             (double)((float)1.9353071795864769e-3));
    float q = rintf(x * 0.15915494309189535f);
    float r = fmaf(q, -C1, x);
    r = fmaf(q, -C2, r);
    r = fmaf(q, -C3, r);
    sincosf(r, s, c);
}

// ============ kernel 1: merged setup (knn | invert | transpose) ===============
// blocks [0,512): knn; [512,539): invert; [539,843): weight transpose.
__global__ __launch_bounds__(256) void setup_kernel(
    const float* __restrict__ pts, const float* __restrict__ kp,
    const float* __restrict__ trans,
    const float* __restrict__ W1, const float* __restrict__ W2,
    const float* __restrict__ W3,
    __half* __restrict__ W1h, __half* __restrict__ W2h, __half* __restrict__ W3h)
{
    __shared__ float4 sk[KRANGE];          // knn
    __shared__ float  tile[32][33];        // transpose
    const int b   = blockIdx.x;
    const int tid = threadIdx.x;

    if (b < 512) {
        // ---------------- KNN ----------------
        int pt = (b & 63) * 256 + tid;
        int ks = (b >> 6) * KRANGE;
        int ke = min(ks + KRANGE, NV);
        int n  = ke - ks;

        for (int i = tid; i < n; i += 256) {
            int vv = ks + i;
            float kx = kp[vv*3], ky = kp[vv*3+1], kz = kp[vv*3+2];
            sk[i] = make_float4(kx, ky, kz, -0.5f*(kx*kx + ky*ky + kz*kz));
        }
        __syncthreads();

        float px = pts[pt*6], py = pts[pt*6+1], pz = pts[pt*6+2];
        float b0 = -1e30f, b1 = -1e30f;
        int   i0 = ks, i1 = ks;

        int i = 0;
#pragma unroll 1
        for (; i + 4 <= n; i += 4) {
#pragma unroll
            for (int u = 0; u < 4; u += 2) {
                float4 k0 = sk[i+u];
                float4 k1 = sk[i+u+1];
                float s0 = fmaf(px, k0.x, fmaf(py, k0.y, fmaf(pz, k0.z, k0.w)));
                float s1 = fmaf(px, k1.x, fmaf(py, k1.y, fmaf(pz, k1.z, k1.w)));
                if (s0 > b0) { b0 = s0; i0 = ks + i + u; }
                if (s1 > b1) { b1 = s1; i1 = ks + i + u + 1; }
            }
        }
        for (; i < n; i++) {
            float4 k = sk[i];
            float s = fmaf(px, k.x, fmaf(py, k.y, fmaf(pz, k.z, k.w)));
            if (s > b0) { b0 = s; i0 = ks + i; }
        }
        auto pack = [](float sc, int idx) {
            unsigned int ub = __float_as_uint(-sc);
            ub = (ub & 0x80000000u) ? ~ub : (ub | 0x80000000u);
            return ((unsigned long long)ub << 32) | (unsigned int)idx;
        };
        unsigned long long p0 = pack(b0, i0), p1 = pack(b1, i1);
        g_part[(size_t)(b >> 6) * NPTS + pt] = p0 < p1 ? p0 : p1;

    } else if (b < 539) {
        // ---------------- invert 4x4 ----------------
        int v = (b - 512) * 256 + tid;
        if (v >= NV) return;
        float m[16];
#pragma unroll
        for (int k = 0; k < 16; k++) m[k] = trans[k * NV + v];

        float i0  =  m[5]*m[10]*m[15] - m[5]*m[11]*m[14] - m[9]*m[6]*m[15] + m[9]*m[7]*m[14] + m[13]*m[6]*m[11] - m[13]*m[7]*m[10];
        float i4  = -m[4]*m[10]*m[15] + m[4]*m[11]*m[14] + m[8]*m[6]*m[15] - m[8]*m[7]*m[14] - m[12]*m[6]*m[11] + m[12]*m[7]*m[10];
        float i8  =  m[4]*m[9]*m[15]  - m[4]*m[11]*m[13] - m[8]*m[5]*m[15] + m[8]*m[7]*m[13] + m[12]*m[5]*m[11] - m[12]*m[7]*m[9];
        float i12 = -m[4]*m[9]*m[14]  + m[4]*m[10]*m[13] + m[8]*m[5]*m[14] - m[8]*m[6]*m[13] - m[12]*m[5]*m[10] + m[12]*m[6]*m[9];
        float i1  = -m[1]*m[10]*m[15] + m[1]*m[11]*m[14] + m[9]*m[2]*m[15] - m[9]*m[3]*m[14] - m[13]*m[2]*m[11] + m[13]*m[3]*m[10];
        float i5  =  m[0]*m[10]*m[15] - m[0]*m[11]*m[14] - m[8]*m[2]*m[15] + m[8]*m[3]*m[14] + m[12]*m[2]*m[11] - m[12]*m[3]*m[10];
        float i9  = -m[0]*m[9]*m[15]  + m[0]*m[11]*m[13] + m[8]*m[1]*m[15] - m[8]*m[3]*m[13] - m[12]*m[1]*m[11] + m[12]*m[3]*m[9];
        float i2  =  m[1]*m[6]*m[15]  - m[1]*m[7]*m[14]  - m[5]*m[2]*m[15] + m[5]*m[3]*m[14] + m[13]*m[2]*m[7]  - m[13]*m[3]*m[6];
        float i6  = -m[0]*m[6]*m[15]  + m[0]*m[7]*m[14]  + m[4]*m[2]*m[15] - m[4]*m[3]*m[14] - m[12]*m[2]*m[7]  + m[12]*m[3]*m[6];
        float i10 =  m[0]*m[5]*m[15]  - m[0]*m[7]*m[13]  - m[4]*m[1]*m[15] + m[4]*m[3]*m[13] + m[12]*m[1]*m[7]  - m[12]*m[3]*m[5];

        float det = m[0]*i0 + m[1]*i4 + m[2]*i8 + m[3]*i12;
        float id  = 1.0f / det;
        float* R = g_Rinv + v * 9;
        R[0] = i0*id;  R[1] = i1*id;  R[2] = i2*id;
        R[3] = i4*id;  R[4] = i5*id;  R[5] = i6*id;
        R[6] = i8*id;  R[7] = i9*id;  R[8] = i10*id;

    } else {
        // ---------------- weight transpose to fp16 ----------------
        int u = b - 539;
        const float* W; __half* Wh; int K, ldk, kb, nb;
        if (u < 176)      { W = W1; Wh = W1h; K = 700; ldk = LDF; kb = (u % 22) * 32; nb = (u / 22) * 32; }
        else if (u < 240) { u -= 176; W = W2; Wh = W2h; K = 256; ldk = 256; kb = (u % 8) * 32; nb = (u / 8) * 32; }
        else              { u -= 240; W = W3; Wh = W3h; K = 256; ldk = 256; kb = (u % 8) * 32; nb = (u / 8) * 32; }

        int tx = tid & 31, ty = tid >> 5;
#pragma unroll
        for (int i = 0; i < 4; i++) {
            int k = kb + ty + i * 8;
            tile[ty + i * 8][tx] = (k < K) ? W[(size_t)k * 256 + nb + tx] : 0.0f;
        }
        __syncthreads();
#pragma unroll
        for (int i = 0; i < 4; i++) {
            int n = nb + ty + i * 8;
            Wh[(size_t)n * ldk + kb + tx] = __float2half_rn(tile[tx][ty + i * 8]);
        }
    }
}

// ---------------- kernel 2: feature build (fused knn-reduce + recurrence) ----
__global__ __launch_bounds__(256) void feat_kernel(const float* __restrict__ pts,
                                                   const float* __restrict__ kp,
                                                   const int*   __restrict__ nbr,
                                                   const float* __restrict__ rest,
                                                   const float* __restrict__ lat,
                                                   float*       __restrict__ out) {
    int gw   = (blockIdx.x * blockDim.x + threadIdx.x) >> 5;
    int lane = threadIdx.x & 31;
    if (gw >= NPTS) return;

    unsigned long long pv = (lane < SPLIT) ? g_part[(size_t)lane * NPTS + gw] : ~0ull;
    unsigned long long o;
    o = __shfl_xor_sync(0xffffffffu, pv, 1); if (o < pv) pv = o;
    o = __shfl_xor_sync(0xffffffffu, pv, 2); if (o < pv) pv = o;
    o = __shfl_xor_sync(0xffffffffu, pv, 4); if (o < pv) pv = o;
    int kidx = (int)(__shfl_sync(0xffffffffu, pv, 0) & 0xFFFFFFFFull);

    float px = pts[gw*6], py = pts[gw*6+1], pz = pts[gw*6+2];

    int vj = (lane < 7) ? nbr[kidx*7 + lane] : 0;
    int j  = (lane < 21) ? (lane / 3) : ((lane < 28) ? (lane - 21) : 0);
    int v  = __shfl_sync(0xffffffffu, vj, j);

    float vf = 0.0f;
    if (lane < 21) {
        vf = rest[v*3 + (lane % 3)];
    } else if (lane < 28) {
        float dx = px - kp[v*3], dy = py - kp[v*3+1], dz = pz - kp[v*3+2];
        vf = sqrtf(dx*dx + dy*dy + dz*dz);
    }

    size_t base = (size_t)gw * LDF;
    if (lane < 28) {
        g_featH[base + lane] = __float2half_rn(vf);
        float s, c;
        sincos_acc(vf, &s, &c);
#pragma unroll
        for (int k = 0; k < 10; k++) {
            g_featH[base + 28  + k*28 + lane] = __float2half_rn(s);
            g_featH[base + 308 + k*28 + lane] = __float2half_rn(c);
            float sn = 2.0f * s * c;
            float cn = fmaf(-2.0f * s, s, 1.0f);
            s = sn; c = cn;
        }
    }
    if (lane < 4) g_featH[base + 700 + lane] = __float2half_rn(0.0f);

#pragma unroll
    for (int it = 0; it < 4; it++) {
        int l  = it * 32 + lane;
        int jj = (l < 112) ? (l >> 4) : 0;
        int vv = __shfl_sync(0xffffffffu, vj, jj);
        if (l < 112) g_featH[base + 588 + l] = __float2half_rn(lat[vv*16 + (l & 15)]);
    }

    if (lane == 0) {
        float dx = px - kp[kidx*3], dy = py - kp[kidx*3+1], dz = pz - kp[kidx*3+2];
        const float* R = g_Rinv + kidx * 9;
        float d0 = R[0]*dx + R[1]*dy + R[2]*dz;
        float d1 = R[3]*dx + R[4]*dy + R[5]*dz;
        float d2 = R[6]*dx + R[7]*dy + R[8]*dz;
        float nn = sqrtf(d0*d0 + d1*d1 + d2*d2);
        float iv = 1.0f / fmaxf(nn, 1e-12f);
        d0 *= iv; d1 *= iv; d2 *= iv;
        float* op = out + (size_t)gw * 283 + 256;
        op[0] = d0; op[1] = d1; op[2] = d2;
        float dir[3] = {d0, d1, d2};
#pragma unroll
        for (int c = 0; c < 3; c++) {
            float s, cc;
            sincos_acc(dir[c], &s, &cc);
#pragma unroll
            for (int k = 0; k < 4; k++) {
                op[3  + k*3 + c] = s;
                op[15 + k*3 + c] = cc;
                float sn = 2.0f * s * cc;
                float cn = fmaf(-2.0f * s, s, 1.0f);
                s = sn; cc = cn;
            }
        }
    }
}

// ---------------- kernel 3: fused 3-layer MLP (fp16 HMMA) --------------------
// CTA: 128 rows x N=256, 512 threads (16 warps, warp tile 32x64).
// h1/h2 live in smem between layers.
#define PADH    40
#define ATILE   (128 * PADH * 2)           // 10240 B
#define BTILE   (256 * PADH * 2)           // 20480 B
#define BUFB    (ATILE + BTILE)            // 30720 B
#define SM_H    (2 * BUFB)                 // 61440: h-tile region start
#define HCHUNK  (128 * PADH)               // halves per 32-K chunk block
#define MLP_SMEM (SM_H + 8 * HCHUNK * 2)   // 61440 + 81920 = 143360 B

__global__ __launch_bounds__(512, 1) void mlp_fused(
    const __half* __restrict__ feat,
    const __half* __restrict__ W1, const __half* __restrict__ W2,
    const __half* __restrict__ W3,
    const float* __restrict__ b1, const float* __restrict__ b2,
    const float* __restrict__ b3,
    float* __restrict__ out)
{
    extern __shared__ char sm[];
    const int tid  = threadIdx.x;
    const int wid  = tid >> 5, lane = tid & 31;
    const int g    = lane >> 2, t = lane & 3;
    const int m0   = blockIdx.x * 128;
    const int m0w  = (wid >> 2) * 32, n0w = (wid & 3) * 64;
    const uint32_t smb = smem_u32(sm);
    const uint32_t sH  = smb + SM_H;
    __half* Hs = (__half*)(sm + SM_H);

    const int arow = lane & 15;
    const int asel = (lane >> 4) << 3;
    const int brow = (lane & 7) + ((lane & 16) ? 8 : 0);
    const int bsel = (lane & 8) ? 8 : 0;

    float acc[2][8][4];

    auto zacc = [&]() {
#pragma unroll
        for (int mi = 0; mi < 2; mi++)
#pragma unroll
            for (int ni = 0; ni < 8; ni++)
#pragma unroll
                for (int q = 0; q < 4; q++) acc[mi][ni][q] = 0.0f;
    };

    auto issueA = [&](int ch) {   // feat -> A tile (layer 1 only)
        const int k0 = ch * 32;
        uint32_t base = smb + (ch & 1) * BUFB;
        int r = tid >> 2, c = (tid & 3) * 8;
        cpa16(base + (uint32_t)(r * PADH + c) * 2, feat + (size_t)(m0 + r) * LDF + k0 + c);
    };
    auto issueB = [&](const __half* W, int ldw, int ch) {
        const int k0 = ch * 32;
        uint32_t base = smb + (ch & 1) * BUFB + ATILE;
#pragma unroll
        for (int i = 0; i < 2; i++) {
            int s = tid + i * 512;
            int r = s >> 2, c = (s & 3) * 8;
            cpa16(base + (uint32_t)(r * PADH + c) * 2, W + (size_t)r * ldw + k0 + c);
        }
    };
    auto compute = [&](uint32_t sA, uint32_t sB) {
#pragma unroll
        for (int ks = 0; ks < 2; ks++) {
            const int kc = ks * 16;
            uint32_t ah[2][4];
#pragma unroll
            for (int mi = 0; mi < 2; mi++)
                ldm4(ah[mi], sA + (uint32_t)((m0w + mi * 16 + arow) * PADH + kc + asel) * 2);
#pragma unroll
            for (int ph = 0; ph < 2; ph++) {
                uint32_t bh[2][4];
#pragma unroll
                for (int pp = 0; pp < 2; pp++) {
                    int p = ph * 2 + pp;
                    ldm4(bh[pp], sB + (uint32_t)((n0w + p * 16 + brow) * PADH + kc + bsel) * 2);
                }
#pragma unroll
                for (int pp = 0; pp < 2; pp++)
#pragma unroll
                    for (int q = 0; q < 2; q++)
#pragma unroll
                        for (int mi = 0; mi < 2; mi++)
                            mma16816(acc[mi][(ph*2+pp)*2+q], ah[mi], bh[pp][q*2], bh[pp][q*2+1]);
            }
        }
    };
    auto epi_smem = [&](const float* bias) {   // relu + fp16 -> Hs (chunk-tiled)
#pragma unroll
        for (int mi = 0; mi < 2; mi++) {
            int row = m0w + mi * 16 + g;
#pragma unroll
            for (int ni = 0; ni < 8; ni++) {
                int col = n0w + ni * 8 + 2 * t;
                float c0 = bias[col], c1 = bias[col + 1];
                float v0 = fmaxf(acc[mi][ni][0] + c0, 0.f);
                float v1 = fmaxf(acc[mi][ni][1] + c1, 0.f);
                float v2 = fmaxf(acc[mi][ni][2] + c0, 0.f);
                float v3 = fmaxf(acc[mi][ni][3] + c1, 0.f);
                int blk = (col >> 5) * HCHUNK, cc = col & 31;
                *(__half2*)&Hs[blk + row * PADH + cc] =
                    __halves2half2(__float2half_rn(v0), __float2half_rn(v1));
                *(__half2*)&Hs[blk + (row + 8) * PADH + cc] =
                    __halves2half2(__float2half_rn(v2), __float2half_rn(v3));
            }
        }
    };

    // ================= layer 1: feat(704) -> h1 =================
    zacc();
    issueA(0); issueB(W1, LDF, 0); CPA_COMMIT();
    for (int ch = 0; ch < 22; ch++) {
        if (ch + 1 < 22) {
            issueA(ch + 1); issueB(W1, LDF, ch + 1); CPA_COMMIT();
            asm volatile("cp.async.wait_group 1;" ::: "memory");
        } else {
            asm volatile("cp.async.wait_group 0;" ::: "memory");
        }
        __syncthreads();
        uint32_t base = smb + (ch & 1) * BUFB;
        compute(base, base + ATILE);
        __syncthreads();
    }
    epi_smem(b1);
    __syncthreads();

    // ================= layer 2: h1 -> h2 (in place) =================
    zacc();
    issueB(W2, 256, 0); CPA_COMMIT();
    for (int ch = 0; ch < 8; ch++) {
        if (ch + 1 < 8) {
            issueB(W2, 256, ch + 1); CPA_COMMIT();
            asm volatile("cp.async.wait_group 1;" ::: "memory");
        } else {
            asm volatile("cp.async.wait_group 0;" ::: "memory");
        }
        __syncthreads();
        compute(sH + (uint32_t)ch * HCHUNK * 2, smb + (ch & 1) * BUFB + ATILE);
        __syncthreads();
    }
    epi_smem(b2);           // overwrites h1 with h2 (all reads done: loop-end sync)
    __syncthreads();

    // ================= layer 3: h2 -> out =================
    zacc();
    issueB(W3, 256, 0); CPA_COMMIT();
    for (int ch = 0; ch < 8; ch++) {
        if (ch + 1 < 8) {
            issueB(W3, 256, ch + 1); CPA_COMMIT();
            asm volatile("cp.async.wait_group 1;" ::: "memory");
        } else {
            asm volatile("cp.async.wait_group 0;" ::: "memory");
        }
        __syncthreads();
        compute(sH + (uint32_t)ch * HCHUNK * 2, smb + (ch & 1) * BUFB + ATILE);
        __syncthreads();
    }
    // epilogue -> global fp32, ldc 283, no relu
#pragma unroll
    for (int mi = 0; mi < 2; mi++) {
        int row = m0 + m0w + mi * 16 + g;
#pragma unroll
        for (int ni = 0; ni < 8; ni++) {
            int col = n0w + ni * 8 + 2 * t;
            float c0 = b3[col], c1 = b3[col + 1];
            out[(size_t)row * 283 + col]           = acc[mi][ni][0] + c0;
            out[(size_t)row * 283 + col + 1]       = acc[mi][ni][1] + c1;
            out[(size_t)(row + 8) * 283 + col]     = acc[mi][ni][2] + c0;
            out[(size_t)(row + 8) * 283 + col + 1] = acc[mi][ni][3] + c1;
        }
    }
}

// ---------------- launch -----------------------------------------------------
extern "C" void kernel_launch(void* const* d_in, const int* in_sizes, int n_in,
                              void* d_out, int out_size) {
    const float* pts   = (const float*)d_in[0];
    const float* kp    = (const float*)d_in[1];
    const float* trans = (const float*)d_in[2];
    const int*   nbr   = (const int*)  d_in[3];
    const float* rest  = (const float*)d_in[4];
    const float* lat   = (const float*)d_in[5];
    const float* W1    = (const float*)d_in[6];
    const float* b1    = (const float*)d_in[7];
    const float* W2    = (const float*)d_in[8];
    const float* b2    = (const float*)d_in[9];
    const float* W3    = (const float*)d_in[10];
    const float* b3    = (const float*)d_in[11];
    float*       out   = (float*)d_out;

    void *pFH, *w1h, *w2h, *w3h;
    cudaGetSymbolAddress(&pFH, g_featH);
    cudaGetSymbolAddress(&w1h, g_W1h);
    cudaGetSymbolAddress(&w2h, g_W2h);
    cudaGetSymbolAddress(&w3h, g_W3h);

    cudaFuncSetAttribute((const void*)mlp_fused,
                         cudaFuncAttributeMaxDynamicSharedMemorySize, MLP_SMEM);

    setup_kernel<<<843, 256>>>(pts, kp, trans, W1, W2, W3,
                               (__half*)w1h, (__half*)w2h, (__half*)w3h);
    feat_kernel<<<NPTS / 8, 256>>>(pts, kp, nbr, rest, lat, out);
    mlp_fused<<<NPTS / 128, 512, MLP_SMEM>>>(
        (const __half*)pFH, (const __half*)w1h, (const __half*)w2h,
        (const __half*)w3h, b1, b2, b3, out);
}

// round 11
// speedup vs baseline: 2.5536x; 1.0597x over previous
#include <cuda_runtime.h>
#include <cuda_fp16.h>
#include <cstdint>
#include <math.h>

#define NV      6890
#define NPTS    16384
#define SPLIT   32
#define KRANGE  216      // ceil(6890/32)
#define LDF     704
#define PPT     4        // points per thread in knn

// ---------------- scratch (device globals) -----------------------------------
__device__ __align__(16) __half  g_featH[(size_t)NPTS * LDF];
__device__ __align__(16) __half  g_W1h[(size_t)256 * LDF];
__device__ __align__(16) __half  g_W2h[(size_t)256 * 256];
__device__ __align__(16) __half  g_W3h[(size_t)256 * 256];
__device__ float                 g_Rinv[NV * 9];
__device__ unsigned long long    g_part[(size_t)SPLIT * NPTS];

// ======================= small PTX helpers ===================================
__device__ __forceinline__ uint32_t smem_u32(const void* p) {
    uint32_t a;
    asm("{ .reg .u64 t; cvta.to.shared.u64 t, %1; cvt.u32.u64 %0, t; }" : "=r"(a) : "l"(p));
    return a;
}
__device__ __forceinline__ void cpa16(uint32_t dst, const void* src) {
    asm volatile("cp.async.cg.shared.global [%0], [%1], 16;" :: "r"(dst), "l"(src));
}
#define CPA_COMMIT() asm volatile("cp.async.commit_group;" ::: "memory")

__device__ __forceinline__ void ldm4(uint32_t* r, uint32_t addr) {
    asm volatile("ldmatrix.sync.aligned.m8n8.x4.shared.b16 {%0,%1,%2,%3}, [%4];"
                 : "=r"(r[0]), "=r"(r[1]), "=r"(r[2]), "=r"(r[3]) : "r"(addr));
}
__device__ __forceinline__ void mma16816(float* c, const uint32_t* a, uint32_t b0, uint32_t b1) {
    asm volatile(
        "mma.sync.aligned.m16n8k16.row.col.f32.f16.f16.f32 "
        "{%0,%1,%2,%3}, {%4,%5,%6,%7}, {%8,%9}, {%0,%1,%2,%3};"
        : "+f"(c[0]), "+f"(c[1]), "+f"(c[2]), "+f"(c[3])
        : "r"(a[0]), "r"(a[1]), "r"(a[2]), "r"(a[3]), "r"(b0), "r"(b1));
}

// ---------------- accurate fp32 sincos (no FP64) -----------------------------
__device__ __forceinline__ void sincos_acc(float x, float* s, float* c) {
    const float C1 = 6.28125f;
    const float C2 = (float)1.9353071795864769e-3;
    const float C3 = (float)(6.283185307179586476925286766559 - 6.28125 -
                             (double)((float)1.9353071795864769e-3));
    float q = rintf(x * 0.15915494309189535f);
    float r = fmaf(q, -C1, x);
    r = fmaf(q, -C2, r);
    r = fmaf(q, -C3, r);
    sincosf(r, s, c);
}

// ============ kernel 1: merged setup (knn | invert | transpose) ===============
// blocks [0,512): knn (32 splits x 16 point-blocks); [512,539): invert;
// [539,843): weight transpose.
__global__ __launch_bounds__(256) void setup_kernel(
    const float* __restrict__ pts, const float* __restrict__ kp,
    const float* __restrict__ trans,
    const float* __restrict__ W1, const float* __restrict__ W2,
    const float* __restrict__ W3,
    __half* __restrict__ W1h, __half* __restrict__ W2h, __half* __restrict__ W3h)
{
    __shared__ float4 sk[KRANGE];          // knn
    __shared__ float  tile[32][33];        // transpose
    const int b   = blockIdx.x;
    const int tid = threadIdx.x;

    if (b < 512) {
        // ---------------- KNN: 4 points/thread ----------------
        const int ptb = b & 15;            // 16 point-blocks of 1024 points
        const int spl = b >> 4;            // 32 keypoint splits
        const int ks  = spl * KRANGE;
        const int ke  = min(ks + KRANGE, NV);
        const int n   = ke - ks;

        for (int i = tid; i < n; i += 256) {
            int vv = ks + i;
            float kx = kp[vv*3], ky = kp[vv*3+1], kz = kp[vv*3+2];
            sk[i] = make_float4(kx, ky, kz, -0.5f*(kx*kx + ky*ky + kz*kz));
        }
        __syncthreads();

        const int pt0 = ptb * 1024 + tid;
        float px[PPT], py[PPT], pz[PPT], bs[PPT];
        int   bi[PPT];
#pragma unroll
        for (int j = 0; j < PPT; j++) {
            int pt = pt0 + j * 256;
            px[j] = pts[pt*6]; py[j] = pts[pt*6+1]; pz[j] = pts[pt*6+2];
            bs[j] = -1e30f; bi[j] = ks;
        }

        int i = 0;
#pragma unroll 1
        for (; i + 2 <= n; i += 2) {
#pragma unroll
            for (int u = 0; u < 2; u++) {
                float4 k = sk[i + u];
#pragma unroll
                for (int j = 0; j < PPT; j++) {
                    float s = fmaf(px[j], k.x, fmaf(py[j], k.y, fmaf(pz[j], k.z, k.w)));
                    if (s > bs[j]) { bs[j] = s; bi[j] = ks + i + u; }
                }
            }
        }
        if (i < n) {
            float4 k = sk[i];
#pragma unroll
            for (int j = 0; j < PPT; j++) {
                float s = fmaf(px[j], k.x, fmaf(py[j], k.y, fmaf(pz[j], k.z, k.w)));
                if (s > bs[j]) { bs[j] = s; bi[j] = ks + i; }
            }
        }

#pragma unroll
        for (int j = 0; j < PPT; j++) {
            unsigned int ub = __float_as_uint(-bs[j]);
            ub = (ub & 0x80000000u) ? ~ub : (ub | 0x80000000u);
            g_part[(size_t)spl * NPTS + pt0 + j * 256] =
                ((unsigned long long)ub << 32) | (unsigned int)bi[j];
        }

    } else if (b < 539) {
        // ---------------- invert 4x4 ----------------
        int v = (b - 512) * 256 + tid;
        if (v >= NV) return;
        float m[16];
#pragma unroll
        for (int k = 0; k < 16; k++) m[k] = trans[k * NV + v];

        float i0  =  m[5]*m[10]*m[15] - m[5]*m[11]*m[14] - m[9]*m[6]*m[15] + m[9]*m[7]*m[14] + m[13]*m[6]*m[11] - m[13]*m[7]*m[10];
        float i4  = -m[4]*m[10]*m[15] + m[4]*m[11]*m[14] + m[8]*m[6]*m[15] - m[8]*m[7]*m[14] - m[12]*m[6]*m[11] + m[12]*m[7]*m[10];
        float i8  =  m[4]*m[9]*m[15]  - m[4]*m[11]*m[13] - m[8]*m[5]*m[15] + m[8]*m[7]*m[13] + m[12]*m[5]*m[11] - m[12]*m[7]*m[9];
        float i12 = -m[4]*m[9]*m[14]  + m[4]*m[10]*m[13] + m[8]*m[5]*m[14] - m[8]*m[6]*m[13] - m[12]*m[5]*m[10] + m[12]*m[6]*m[9];
        float i1  = -m[1]*m[10]*m[15] + m[1]*m[11]*m[14] + m[9]*m[2]*m[15] - m[9]*m[3]*m[14] - m[13]*m[2]*m[11] + m[13]*m[3]*m[10];
        float i5  =  m[0]*m[10]*m[15] - m[0]*m[11]*m[14] - m[8]*m[2]*m[15] + m[8]*m[3]*m[14] + m[12]*m[2]*m[11] - m[12]*m[3]*m[10];
        float i9  = -m[0]*m[9]*m[15]  + m[0]*m[11]*m[13] + m[8]*m[1]*m[15] - m[8]*m[3]*m[13] - m[12]*m[1]*m[11] + m[12]*m[3]*m[9];
        float i2  =  m[1]*m[6]*m[15]  - m[1]*m[7]*m[14]  - m[5]*m[2]*m[15] + m[5]*m[3]*m[14] + m[13]*m[2]*m[7]  - m[13]*m[3]*m[6];
        float i6  = -m[0]*m[6]*m[15]  + m[0]*m[7]*m[14]  + m[4]*m[2]*m[15] - m[4]*m[3]*m[14] - m[12]*m[2]*m[7]  + m[12]*m[3]*m[6];
        float i10 =  m[0]*m[5]*m[15]  - m[0]*m[7]*m[13]  - m[4]*m[1]*m[15] + m[4]*m[3]*m[13] + m[12]*m[1]*m[7]  - m[12]*m[3]*m[5];

        float det = m[0]*i0 + m[1]*i4 + m[2]*i8 + m[3]*i12;
        float id  = 1.0f / det;
        float* R = g_Rinv + v * 9;
        R[0] = i0*id;  R[1] = i1*id;  R[2] = i2*id;
        R[3] = i4*id;  R[4] = i5*id;  R[5] = i6*id;
        R[6] = i8*id;  R[7] = i9*id;  R[8] = i10*id;

    } else {
        // ---------------- weight transpose to fp16 ----------------
        int u = b - 539;
        const float* W; __half* Wh; int K, ldk, kb, nb;
        if (u < 176)      { W = W1; Wh = W1h; K = 700; ldk = LDF; kb = (u % 22) * 32; nb = (u / 22) * 32; }
        else if (u < 240) { u -= 176; W = W2; Wh = W2h; K = 256; ldk = 256; kb = (u % 8) * 32; nb = (u / 8) * 32; }
        else              { u -= 240; W = W3; Wh = W3h; K = 256; ldk = 256; kb = (u % 8) * 32; nb = (u / 8) * 32; }

        int tx = tid & 31, ty = tid >> 5;
#pragma unroll
        for (int i = 0; i < 4; i++) {
            int k = kb + ty + i * 8;
            tile[ty + i * 8][tx] = (k < K) ? W[(size_t)k * 256 + nb + tx] : 0.0f;
        }
        __syncthreads();
#pragma unroll
        for (int i = 0; i < 4; i++) {
            int n = nb + ty + i * 8;
            Wh[(size_t)n * ldk + kb + tx] = __float2half_rn(tile[tx][ty + i * 8]);
        }
    }
}

// ---------------- kernel 2: feature build (fused knn-reduce + recurrence) ----
__global__ __launch_bounds__(256) void feat_kernel(const float* __restrict__ pts,
                                                   const float* __restrict__ kp,
                                                   const int*   __restrict__ nbr,
                                                   const float* __restrict__ rest,
                                                   const float* __restrict__ lat,
                                                   float*       __restrict__ out) {
    int gw   = (blockIdx.x * blockDim.x + threadIdx.x) >> 5;
    int lane = threadIdx.x & 31;
    if (gw >= NPTS) return;

    // fused 32-way knn reduce (min of packed u64)
    unsigned long long pv = g_part[(size_t)lane * NPTS + gw];
    unsigned long long o;
    o = __shfl_xor_sync(0xffffffffu, pv, 1);  if (o < pv) pv = o;
    o = __shfl_xor_sync(0xffffffffu, pv, 2);  if (o < pv) pv = o;
    o = __shfl_xor_sync(0xffffffffu, pv, 4);  if (o < pv) pv = o;
    o = __shfl_xor_sync(0xffffffffu, pv, 8);  if (o < pv) pv = o;
    o = __shfl_xor_sync(0xffffffffu, pv, 16); if (o < pv) pv = o;
    int kidx = (int)(pv & 0xFFFFFFFFull);

    float px = pts[gw*6], py = pts[gw*6+1], pz = pts[gw*6+2];

    int vj = (lane < 7) ? nbr[kidx*7 + lane] : 0;
    int j  = (lane < 21) ? (lane / 3) : ((lane < 28) ? (lane - 21) : 0);
    int v  = __shfl_sync(0xffffffffu, vj, j);

    float vf = 0.0f;
    if (lane < 21) {
        vf = rest[v*3 + (lane % 3)];
    } else if (lane < 28) {
        float dx = px - kp[v*3], dy = py - kp[v*3+1], dz = pz - kp[v*3+2];
        vf = sqrtf(dx*dx + dy*dy + dz*dz);
    }

    size_t base = (size_t)gw * LDF;
    if (lane < 28) {
        g_featH[base + lane] = __float2half_rn(vf);
        float s, c;
        sincos_acc(vf, &s, &c);
#pragma unroll
        for (int k = 0; k < 10; k++) {
            g_featH[base + 28  + k*28 + lane] = __float2half_rn(s);
            g_featH[base + 308 + k*28 + lane] = __float2half_rn(c);
            float sn = 2.0f * s * c;
            float cn = fmaf(-2.0f * s, s, 1.0f);
            s = sn; c = cn;
        }
    }
    if (lane < 4) g_featH[base + 700 + lane] = __float2half_rn(0.0f);

#pragma unroll
    for (int it = 0; it < 4; it++) {
        int l  = it * 32 + lane;
        int jj = (l < 112) ? (l >> 4) : 0;
        int vv = __shfl_sync(0xffffffffu, vj, jj);
        if (l < 112) g_featH[base + 588 + l] = __float2half_rn(lat[vv*16 + (l & 15)]);
    }

    if (lane == 0) {
        float dx = px - kp[kidx*3], dy = py - kp[kidx*3+1], dz = pz - kp[kidx*3+2];
        const float* R = g_Rinv + kidx * 9;
        float d0 = R[0]*dx + R[1]*dy + R[2]*dz;
        float d1 = R[3]*dx + R[4]*dy + R[5]*dz;
        float d2 = R[6]*dx + R[7]*dy + R[8]*dz;
        float nn = sqrtf(d0*d0 + d1*d1 + d2*d2);
        float iv = 1.0f / fmaxf(nn, 1e-12f);
        d0 *= iv; d1 *= iv; d2 *= iv;
        float* op = out + (size_t)gw * 283 + 256;
        op[0] = d0; op[1] = d1; op[2] = d2;
        float dir[3] = {d0, d1, d2};
#pragma unroll
        for (int c = 0; c < 3; c++) {
            float s, cc;
            sincos_acc(dir[c], &s, &cc);
#pragma unroll
            for (int k = 0; k < 4; k++) {
                op[3  + k*3 + c] = s;
                op[15 + k*3 + c] = cc;
                float sn = 2.0f * s * cc;
                float cn = fmaf(-2.0f * s, s, 1.0f);
                s = sn; cc = cn;
            }
        }
    }
}

// ---------------- kernel 3: fused 3-layer MLP (fp16 HMMA) --------------------
#define PADH    40
#define ATILE   (128 * PADH * 2)           // 10240 B
#define BTILE   (256 * PADH * 2)           // 20480 B
#define BUFB    (ATILE + BTILE)            // 30720 B
#define SM_H    (2 * BUFB)                 // 61440: h-tile region start
#define HCHUNK  (128 * PADH)               // halves per 32-K chunk block
#define MLP_SMEM (SM_H + 8 * HCHUNK * 2)   // 143360 B

__global__ __launch_bounds__(512, 1) void mlp_fused(
    const __half* __restrict__ feat,
    const __half* __restrict__ W1, const __half* __restrict__ W2,
    const __half* __restrict__ W3,
    const float* __restrict__ b1, const float* __restrict__ b2,
    const float* __restrict__ b3,
    float* __restrict__ out)
{
    extern __shared__ char sm[];
    const int tid  = threadIdx.x;
    const int wid  = tid >> 5, lane = tid & 31;
    const int g    = lane >> 2, t = lane & 3;
    const int m0   = blockIdx.x * 128;
    const int m0w  = (wid >> 2) * 32, n0w = (wid & 3) * 64;
    const uint32_t smb = smem_u32(sm);
    const uint32_t sH  = smb + SM_H;
    __half* Hs = (__half*)(sm + SM_H);

    const int arow = lane & 15;
    const int asel = (lane >> 4) << 3;
    const int brow = (lane & 7) + ((lane & 16) ? 8 : 0);
    const int bsel = (lane & 8) ? 8 : 0;

    float acc[2][8][4];

    auto zacc = [&]() {
#pragma unroll
        for (int mi = 0; mi < 2; mi++)
#pragma unroll
            for (int ni = 0; ni < 8; ni++)
#pragma unroll
                for (int q = 0; q < 4; q++) acc[mi][ni][q] = 0.0f;
    };

    auto issueA = [&](int ch) {
        const int k0 = ch * 32;
        uint32_t base = smb + (ch & 1) * BUFB;
        int r = tid >> 2, c = (tid & 3) * 8;
        cpa16(base + (uint32_t)(r * PADH + c) * 2, feat + (size_t)(m0 + r) * LDF + k0 + c);
    };
    auto issueB = [&](const __half* W, int ldw, int ch) {
        const int k0 = ch * 32;
        uint32_t base = smb + (ch & 1) * BUFB + ATILE;
#pragma unroll
        for (int i = 0; i < 2; i++) {
            int s = tid + i * 512;
            int r = s >> 2, c = (s & 3) * 8;
            cpa16(base + (uint32_t)(r * PADH + c) * 2, W + (size_t)r * ldw + k0 + c);
        }
    };
    auto compute = [&](uint32_t sA, uint32_t sB) {
#pragma unroll
        for (int ks = 0; ks < 2; ks++) {
            const int kc = ks * 16;
            uint32_t ah[2][4];
#pragma unroll
            for (int mi = 0; mi < 2; mi++)
                ldm4(ah[mi], sA + (uint32_t)((m0w + mi * 16 + arow) * PADH + kc + asel) * 2);
#pragma unroll
            for (int ph = 0; ph < 2; ph++) {
                uint32_t bh[2][4];
#pragma unroll
                for (int pp = 0; pp < 2; pp++) {
                    int p = ph * 2 + pp;
                    ldm4(bh[pp], sB + (uint32_t)((n0w + p * 16 + brow) * PADH + kc + bsel) * 2);
                }
#pragma unroll
                for (int pp = 0; pp < 2; pp++)
#pragma unroll
                    for (int q = 0; q < 2; q++)
#pragma unroll
                        for (int mi = 0; mi < 2; mi++)
                            mma16816(acc[mi][(ph*2+pp)*2+q], ah[mi], bh[pp][q*2], bh[pp][q*2+1]);
            }
        }
    };
    auto epi_smem = [&](const float* bias) {
#pragma unroll
        for (int mi = 0; mi < 2; mi++) {
            int row = m0w + mi * 16 + g;
#pragma unroll
            for (int ni = 0; ni < 8; ni++) {
                int col = n0w + ni * 8 + 2 * t;
                float c0 = bias[col], c1 = bias[col + 1];
                float v0 = fmaxf(acc[mi][ni][0] + c0, 0.f);
                float v1 = fmaxf(acc[mi][ni][1] + c1, 0.f);
                float v2 = fmaxf(acc[mi][ni][2] + c0, 0.f);
                float v3 = fmaxf(acc[mi][ni][3] + c1, 0.f);
                int blk = (col >> 5) * HCHUNK, cc = col & 31;
                *(__half2*)&Hs[blk + row * PADH + cc] =
                    __halves2half2(__float2half_rn(v0), __float2half_rn(v1));
                *(__half2*)&Hs[blk + (row + 8) * PADH + cc] =
                    __halves2half2(__float2half_rn(v2), __float2half_rn(v3));
            }
        }
    };

    // layer 1
    zacc();
    issueA(0); issueB(W1, LDF, 0); CPA_COMMIT();
    for (int ch = 0; ch < 22; ch++) {
        if (ch + 1 < 22) {
            issueA(ch + 1); issueB(W1, LDF, ch + 1); CPA_COMMIT();
            asm volatile("cp.async.wait_group 1;" ::: "memory");
        } else {
            asm volatile("cp.async.wait_group 0;" ::: "memory");
        }
        __syncthreads();
        uint32_t base = smb + (ch & 1) * BUFB;
        compute(base, base + ATILE);
        __syncthreads();
    }
    epi_smem(b1);
    __syncthreads();

    // layer 2
    zacc();
    issueB(W2, 256, 0); CPA_COMMIT();
    for (int ch = 0; ch < 8; ch++) {
        if (ch + 1 < 8) {
            issueB(W2, 256, ch + 1); CPA_COMMIT();
            asm volatile("cp.async.wait_group 1;" ::: "memory");
        } else {
            asm volatile("cp.async.wait_group 0;" ::: "memory");
        }
        __syncthreads();
        compute(sH + (uint32_t)ch * HCHUNK * 2, smb + (ch & 1) * BUFB + ATILE);
        __syncthreads();
    }
    epi_smem(b2);
    __syncthreads();

    // layer 3
    zacc();
    issueB(W3, 256, 0); CPA_COMMIT();
    for (int ch = 0; ch < 8; ch++) {
        if (ch + 1 < 8) {
            issueB(W3, 256, ch + 1); CPA_COMMIT();
            asm volatile("cp.async.wait_group 1;" ::: "memory");
        } else {
            asm volatile("cp.async.wait_group 0;" ::: "memory");
        }
        __syncthreads();
        compute(sH + (uint32_t)ch * HCHUNK * 2, smb + (ch & 1) * BUFB + ATILE);
        __syncthreads();
    }
#pragma unroll
    for (int mi = 0; mi < 2; mi++) {
        int row = m0 + m0w + mi * 16 + g;
#pragma unroll
        for (int ni = 0; ni < 8; ni++) {
            int col = n0w + ni * 8 + 2 * t;
            float c0 = b3[col], c1 = b3[col + 1];
            out[(size_t)row * 283 + col]           = acc[mi][ni][0] + c0;
            out[(size_t)row * 283 + col + 1]       = acc[mi][ni][1] + c1;
            out[(size_t)(row + 8) * 283 + col]     = acc[mi][ni][2] + c0;
            out[(size_t)(row + 8) * 283 + col + 1] = acc[mi][ni][3] + c1;
        }
    }
}

// ---------------- launch -----------------------------------------------------
extern "C" void kernel_launch(void* const* d_in, const int* in_sizes, int n_in,
                              void* d_out, int out_size) {
    const float* pts   = (const float*)d_in[0];
    const float* kp    = (const float*)d_in[1];
    const float* trans = (const float*)d_in[2];
    const int*   nbr   = (const int*)  d_in[3];
    const float* rest  = (const float*)d_in[4];
    const float* lat   = (const float*)d_in[5];
    const float* W1    = (const float*)d_in[6];
    const float* b1    = (const float*)d_in[7];
    const float* W2    = (const float*)d_in[8];
    const float* b2    = (const float*)d_in[9];
    const float* W3    = (const float*)d_in[10];
    const float* b3    = (const float*)d_in[11];
    float*       out   = (float*)d_out;

    void *pFH, *w1h, *w2h, *w3h;
    cudaGetSymbolAddress(&pFH, g_featH);
    cudaGetSymbolAddress(&w1h, g_W1h);
    cudaGetSymbolAddress(&w2h, g_W2h);
    cudaGetSymbolAddress(&w3h, g_W3h);

    cudaFuncSetAttribute((const void*)mlp_fused,
                         cudaFuncAttributeMaxDynamicSharedMemorySize, MLP_SMEM);

    setup_kernel<<<843, 256>>>(pts, kp, trans, W1, W2, W3,
                               (__half*)w1h, (__half*)w2h, (__half*)w3h);
    feat_kernel<<<NPTS / 8, 256>>>(pts, kp, nbr, rest, lat, out);
    mlp_fused<<<NPTS / 128, 512, MLP_SMEM>>>(
        (const __half*)pFH, (const __half*)w1h, (const __half*)w2h,
        (const __half*)w3h, b1, b2, b3, out);
}